// round 11
// baseline (speedup 1.0000x reference)
#include <cuda_runtime.h>
#include <cuda_fp16.h>
#include <math.h>
#include <stdint.h>

// ---------------- Problem constants (B=1) ----------------
#define T_LEN   4096
#define DMODEL  2048
#define NHEAD   16
#define DHEAD   128
#define NCHUNK  64
#define CLEN    64
#define QKVZ_N  8192
#define MIX_N   6144
#define MDIM    8192

// ---------------- fp32 scratch ----------------
__device__ float g_h   [T_LEN * DMODEL];
__device__ float g_qkvz[T_LEN * QKVZ_N];
__device__ float g_ba  [T_LEN * 32];
__device__ float g_qb  [NHEAD * T_LEN * DHEAD];
__device__ float g_kb  [NHEAD * T_LEN * DHEAD];
__device__ float g_vb  [NHEAD * T_LEN * DHEAD];
__device__ float g_beta[NHEAD * T_LEN];
__device__ float g_g   [NHEAD * T_LEN];
__device__ float g_gcs [NHEAD * T_LEN];
__device__ float g_u   [NHEAD * T_LEN * DHEAD];
__device__ float g_wb  [NHEAD * T_LEN * DHEAD];
__device__ float g_attn[NHEAD * NCHUNK * CLEN * CLEN];
__device__ float g_o   [NHEAD * T_LEN * DHEAD];
__device__ float g_x2  [T_LEN * DMODEL];
__device__ float g_up  [T_LEN * MDIM];

// ---------------- fp16 operand scratch ----------------
__device__ __half b_h16 [T_LEN * DMODEL];
__device__ __half b_oc16[T_LEN * DMODEL];
__device__ __half b_gu16[T_LEN * MDIM];
__device__ __half b_w1 [QKVZ_N * DMODEL];
__device__ __half b_wo [DMODEL * DMODEL];
__device__ __half b_wg [MDIM * DMODEL];
__device__ __half b_wu [MDIM * DMODEL];
__device__ __half b_wd [DMODEL * MDIM];

// ---------------- PTX helpers (sm_103-safe) ----------------
__device__ __forceinline__ uint32_t smem_u32(const void* p) {
    uint32_t a;
    asm("{ .reg .u64 t; cvta.to.shared.u64 t, %1; cvt.u32.u64 %0, t; }" : "=r"(a) : "l"(p));
    return a;
}
#define CP_ASYNC16(d,s) asm volatile("cp.async.cg.shared.global [%0], [%1], 16;" :: "r"(d), "l"(s))
#define CP_COMMIT()     asm volatile("cp.async.commit_group;" ::: "memory")
#define CP_WAIT2()      asm volatile("cp.async.wait_group 2;" ::: "memory")
#define CP_WAIT1()      asm volatile("cp.async.wait_group 1;" ::: "memory")
#define CP_WAIT0()      asm volatile("cp.async.wait_group 0;" ::: "memory")

__device__ __forceinline__ void ldsm4(uint32_t addr, uint32_t* o) {
    uint32_t r0, r1, r2, r3;
    asm volatile("ldmatrix.sync.aligned.m8n8.x4.shared.b16 {%0,%1,%2,%3}, [%4];"
        : "=r"(r0), "=r"(r1), "=r"(r2), "=r"(r3) : "r"(addr));
    o[0] = r0; o[1] = r1; o[2] = r2; o[3] = r3;
}

__device__ __forceinline__ void mma16816(float* d, uint32_t a0, uint32_t a1, uint32_t a2,
                                         uint32_t a3, uint32_t b0, uint32_t b1) {
    float t0 = d[0], t1 = d[1], t2 = d[2], t3 = d[3];
    asm volatile("mma.sync.aligned.m16n8k16.row.col.f32.f16.f16.f32 "
        "{%0,%1,%2,%3},{%4,%5,%6,%7},{%8,%9},{%0,%1,%2,%3};"
        : "+f"(t0), "+f"(t1), "+f"(t2), "+f"(t3)
        : "r"(a0), "r"(a1), "r"(a2), "r"(a3), "r"(b0), "r"(b1));
    d[0] = t0; d[1] = t1; d[2] = t2; d[3] = t3;
}

// ---------------- helpers ----------------
__device__ __forceinline__ float block_reduce_sum(float v, float* shm, int tid, int nthreads) {
    #pragma unroll
    for (int o = 16; o; o >>= 1) v += __shfl_down_sync(0xffffffffu, v, o);
    __syncthreads();
    if ((tid & 31) == 0) shm[tid >> 5] = v;
    __syncthreads();
    int nw = nthreads >> 5;
    float s = (tid < nw) ? shm[tid] : 0.f;
    if (tid < 32) {
        #pragma unroll
        for (int o = 16; o; o >>= 1) s += __shfl_down_sync(0xffffffffu, s, o);
        if (tid == 0) shm[0] = s;
    }
    __syncthreads();
    return shm[0];
}
__device__ __forceinline__ float silu_f(float x) { return x / (1.f + __expf(-x)); }

// ---------------- weight fp32 -> fp16 ----------------
__global__ void cvt16(const float* __restrict__ x, __half* __restrict__ y, int n) {
    int i = (blockIdx.x * blockDim.x + threadIdx.x) * 4;
    if (i >= n) return;
    float4 v = *(const float4*)(x + i);
    __half2* yp = (__half2*)(y + i);
    yp[0] = __halves2half2(__float2half(v.x), __float2half(v.y));
    yp[1] = __halves2half2(__float2half(v.z), __float2half(v.w));
}

// ---------------- RMSNorm + fp16 ----------------
__global__ void rmsnorm_kernel(const float* __restrict__ x, const float* __restrict__ w,
                               float* __restrict__ y, __half* __restrict__ y16) {
    int t = blockIdx.x, tid = threadIdx.x;
    __shared__ float shm[32];
    const float* xr = x + (size_t)t * DMODEL;
    float ss = 0.f;
    for (int d = tid; d < DMODEL; d += 256) { float v = xr[d]; ss += v * v; }
    ss = block_reduce_sum(ss, shm, tid, 256);
    float inv = rsqrtf(ss / (float)DMODEL + 1e-5f);
    for (int d = tid; d < DMODEL; d += 256) {
        float v = xr[d] * inv * w[d];
        y[(size_t)t * DMODEL + d] = v;
        y16[(size_t)t * DMODEL + d] = __float2half(v);
    }
}

// ---------------- HMMA GEMM: 128x128 CTA tile, 4 warps (2x2), 64x64 warp tile ----------------
// C[M,N] = A@B^T (+R). BK=32, 3-buffer cp.async, 2 CTAs/SM.
// Row 64B in smem, chunk swizzle c ^= (row>>1)&3.
#define GSTAGE 16384   // A 8K | B 8K
__global__ void __launch_bounds__(128, 2) gemm_tc(
    const __half* __restrict__ A, const __half* __restrict__ B,
    const float* __restrict__ R, float* __restrict__ C, int M, int N, int K) {
    extern __shared__ char smem_raw[];
    uint32_t sbase = smem_u32(smem_raw);
    int tid = threadIdx.x, lane = tid & 31, warp = tid >> 5;
    int wm = warp >> 1, wn = warp & 1;
    int m0 = blockIdx.y * 128, n0 = blockIdx.x * 128;
    const int TS = K >> 5;

    float acc[4][8][4];
    #pragma unroll
    for (int a = 0; a < 4; a++)
        #pragma unroll
        for (int b = 0; b < 8; b++)
            #pragma unroll
            for (int c = 0; c < 4; c++) acc[a][b][c] = 0.f;

    // ldmatrix offsets (stage-relative), both k-steps
    uint32_t aoff[4][2], boff[4][2];
    {
        int mat = lane >> 3, r = lane & 7;
        #pragma unroll
        for (int mt = 0; mt < 4; mt++) {
            int row = wm * 64 + mt * 16 + ((mat & 1) << 3) + r;
            #pragma unroll
            for (int ks = 0; ks < 2; ks++) {
                int ch = (ks << 1) + (mat >> 1);
                aoff[mt][ks] = row * 64 + ((ch ^ ((row >> 1) & 3)) << 4);
            }
        }
        #pragma unroll
        for (int j = 0; j < 4; j++) {
            int row = wn * 64 + j * 16 + ((mat >> 1) << 3) + r;
            #pragma unroll
            for (int ks = 0; ks < 2; ks++) {
                int ch = (ks << 1) + (mat & 1);
                boff[j][ks] = 8192 + row * 64 + ((ch ^ ((row >> 1) & 3)) << 4);
            }
        }
    }

    // loader: 128 threads, each loads 4 A-chunks (row=tid) + 4 B-chunks (row=tid)
    uint32_t asw[4], bsw[4];
    #pragma unroll
    for (int c = 0; c < 4; c++) {
        uint32_t sw = tid * 64 + ((c ^ ((tid >> 1) & 3)) << 4);
        asw[c] = sw;
        bsw[c] = 8192 + sw;
    }

    auto load_stage = [&](int st) {
        int buf = st % 3;
        int k0 = st << 5;
        uint32_t bb = sbase + buf * GSTAGE;
        const __half* Ar = A + (size_t)(m0 + tid) * K + k0;
        const __half* Br = B + (size_t)(n0 + tid) * K + k0;
        #pragma unroll
        for (int c = 0; c < 4; c++) {
            CP_ASYNC16(bb + asw[c], Ar + c * 8);
            CP_ASYNC16(bb + bsw[c], Br + c * 8);
        }
        CP_COMMIT();
    };

    load_stage(0); load_stage(1); load_stage(2);

    for (int st = 0; st < TS; st++) {
        int rem = TS - 1 - st;
        if (rem >= 2) { CP_WAIT2(); } else if (rem == 1) { CP_WAIT1(); } else { CP_WAIT0(); }
        __syncthreads();

        uint32_t stb = sbase + (st % 3) * GSTAGE;
        #pragma unroll
        for (int ks = 0; ks < 2; ks++) {
            uint32_t af[4][4], bf[4][4];
            #pragma unroll
            for (int mt = 0; mt < 4; mt++) ldsm4(stb + aoff[mt][ks], af[mt]);
            #pragma unroll
            for (int j = 0; j < 4; j++) ldsm4(stb + boff[j][ks], bf[j]);
            #pragma unroll
            for (int mt = 0; mt < 4; mt++)
                #pragma unroll
                for (int j = 0; j < 4; j++) {
                    mma16816(&acc[mt][2 * j][0],     af[mt][0], af[mt][1], af[mt][2], af[mt][3], bf[j][0], bf[j][1]);
                    mma16816(&acc[mt][2 * j + 1][0], af[mt][0], af[mt][1], af[mt][2], af[mt][3], bf[j][2], bf[j][3]);
                }
        }
        __syncthreads();
        if (st + 3 < TS) load_stage(st + 3);
    }

    #pragma unroll
    for (int mt = 0; mt < 4; mt++) {
        #pragma unroll
        for (int nt = 0; nt < 8; nt++) {
            int rr = m0 + wm * 64 + mt * 16 + (lane >> 2);
            int cc = n0 + wn * 64 + nt * 8 + ((lane & 3) << 1);
            float2 v0, v1;
            v0.x = acc[mt][nt][0]; v0.y = acc[mt][nt][1];
            v1.x = acc[mt][nt][2]; v1.y = acc[mt][nt][3];
            if (R != 0) {
                const float2 r0 = *(const float2*)(R + (size_t)rr * N + cc);
                const float2 r1 = *(const float2*)(R + (size_t)(rr + 8) * N + cc);
                v0.x += r0.x; v0.y += r0.y; v1.x += r1.x; v1.y += r1.y;
            }
            *(float2*)(C + (size_t)rr * N + cc) = v0;
            *(float2*)(C + (size_t)(rr + 8) * N + cc) = v1;
        }
    }
}

// ---------------- small-N GEMM for ba ----------------
__global__ void gemm_n32(const float* __restrict__ A, const float* __restrict__ B,
                         float* __restrict__ C, int K) {
    __shared__ float hs[32][65];
    __shared__ float ws[32][65];
    int m0 = blockIdx.x * 32;
    int tid = threadIdx.x;
    int c = tid & 31, r0 = tid >> 5;
    float acc[4] = {0, 0, 0, 0};
    for (int k0 = 0; k0 < K; k0 += 64) {
        __syncthreads();
        for (int idx = tid; idx < 2048; idx += 256) {
            int r = idx >> 6, kk = idx & 63;
            hs[r][kk] = A[(size_t)(m0 + r) * K + k0 + kk];
            ws[r][kk] = B[(size_t)r * K + k0 + kk];
        }
        __syncthreads();
        for (int kk = 0; kk < 64; kk++) {
            float wv = ws[c][kk];
            #pragma unroll
            for (int s = 0; s < 4; s++) acc[s] += hs[r0 + 8 * s][kk] * wv;
        }
    }
    #pragma unroll
    for (int s = 0; s < 4; s++) C[(size_t)(m0 + r0 + 8 * s) * 32 + c] = acc[s];
}

// ---------------- causal conv + silu + l2norm + head split ----------------
__global__ void conv_kernel(const float* __restrict__ qkvz, const float* __restrict__ conv_w,
                            float* __restrict__ qo, float* __restrict__ ko, float* __restrict__ vo) {
    int t = blockIdx.y;
    int wh = blockIdx.x;
    int which = wh >> 4, head = wh & 15;
    int d = threadIdx.x;
    int c = which * 2048 + head * 128 + d;
    float acc = 0.f;
    #pragma unroll
    for (int j = 0; j < 4; j++) {
        int tt = t - 3 + j;
        if (tt >= 0) acc += qkvz[(size_t)tt * QKVZ_N + c] * conv_w[c * 4 + j];
    }
    float s = silu_f(acc);
    size_t oidx = ((size_t)head * T_LEN + t) * DHEAD + d;
    if (which == 2) { vo[oidx] = s; return; }
    __shared__ float shm[32];
    float ss = block_reduce_sum(s * s, shm, d, 128);
    float val = s * rsqrtf(ss + 1e-6f);
    if (which == 0) val *= 0.08838834764831845f;
    (which == 0 ? qo : ko)[oidx] = val;
}

// ---------------- beta / g ----------------
__global__ void betag_kernel(const float* __restrict__ ba, const float* __restrict__ A_log,
                             const float* __restrict__ dt_bias,
                             float* __restrict__ beta, float* __restrict__ g) {
    int idx = blockIdx.x * blockDim.x + threadIdx.x;
    if (idx >= NHEAD * T_LEN) return;
    int t = idx >> 4, h = idx & 15;
    float b = ba[t * 32 + h];
    float a = ba[t * 32 + 16 + h];
    beta[h * T_LEN + t] = 1.f / (1.f + expf(-b));
    float xx = a + dt_bias[h];
    float sp = (xx > 20.f) ? xx : log1pf(expf(xx));
    g[h * T_LEN + t] = -expf(A_log[h]) * sp;
}

// ---------------- within-chunk cumsum of g ----------------
__global__ void gcs_kernel(const float* __restrict__ g, float* __restrict__ gcs) {
    int h = blockIdx.x >> 6, n = blockIdx.x & 63;
    __shared__ float s[64];
    int i = threadIdx.x;
    int base = h * T_LEN + n * 64;
    s[i] = g[base + i];
    __syncthreads();
    for (int off = 1; off < 64; off <<= 1) {
        float v = (i >= off) ? s[i - off] : 0.f;
        __syncthreads();
        s[i] += v;
        __syncthreads();
    }
    gcs[base + i] = s[i];
}

// ---------------- per-chunk prep: A, T=(I+A)^-1, u, w, attn ----------------
struct PrepShm {
    float k[64][128];
    float x[64][128];
    float A[64][64];
    float T[64][64];
    float gcs[64];
    float beta[64];
    float coef[64];
};
extern __shared__ float dyn_smem[];

__global__ void __launch_bounds__(128) prep_kernel(
    const float* __restrict__ gk, const float* __restrict__ gv, const float* __restrict__ gq,
    const float* __restrict__ gbeta, const float* __restrict__ ggcs,
    float* __restrict__ gu, float* __restrict__ gw, float* __restrict__ gattn) {
    PrepShm& S = *(PrepShm*)dyn_smem;
    int n = blockIdx.x, h = blockIdx.y;
    int tid = threadIdx.x;
    int base = h * T_LEN + n * 64;

    if (tid < 64) {
        S.gcs[tid]  = ggcs[base + tid];
        S.beta[tid] = gbeta[base + tid];
    }
    for (int idx = tid; idx < 64 * 128; idx += 128) {
        int i = idx >> 7, d = idx & 127;
        S.k[i][d] = gk[(size_t)(base + i) * DHEAD + d];
    }
    __syncthreads();
    for (int idx = tid; idx < 64 * 128; idx += 128) {
        int i = idx >> 7, d = idx & 127;
        S.x[i][d] = gv[(size_t)(base + i) * DHEAD + d] * S.beta[i];
    }
    for (int idx = tid; idx < 4096; idx += 128) {
        int i = idx >> 6, j = idx & 63;
        float val = 0.f;
        if (j < i) {
            float acc = 0.f;
            #pragma unroll 8
            for (int d = 0; d < 128; d++) {
                int dd = (d + tid) & 127;
                acc += S.k[i][dd] * S.k[j][dd];
            }
            val = acc * S.beta[i] * __expf(S.gcs[i] - S.gcs[j]);
        }
        S.A[i][j] = val;
    }
    __syncthreads();
    if (tid < 64) S.T[0][tid] = (tid == 0) ? 1.f : 0.f;
    __syncthreads();
    for (int i = 1; i < 64; i++) {
        if (tid < 64) {
            float acc = 0.f;
            for (int j = 0; j < i; j++) acc += S.A[i][j] * S.T[j][tid];
            S.T[i][tid] = ((tid == i) ? 1.f : 0.f) - acc;
        }
        __syncthreads();
    }
    if (tid < 64) S.coef[tid] = S.beta[tid] * __expf(S.gcs[tid]);
    __syncthreads();
    for (int idx = tid; idx < 64 * 128; idx += 128) {
        int i = idx >> 7, d = idx & 127;
        float au = 0.f, aw = 0.f;
        for (int j = 0; j <= i; j++) {
            float tij = S.T[i][j];
            au += tij * S.x[j][d];
            aw += tij * S.coef[j] * S.k[j][d];
        }
        gu[(size_t)(base + i) * DHEAD + d] = au;
        gw[(size_t)(base + i) * DHEAD + d] = aw;
    }
    __syncthreads();
    for (int idx = tid; idx < 64 * 128; idx += 128) {
        int i = idx >> 7, d = idx & 127;
        S.x[i][d] = gq[(size_t)(base + i) * DHEAD + d];
    }
    __syncthreads();
    float* attn_out = gattn + ((size_t)(h * 64 + n)) * 64 * 64;
    for (int idx = tid; idx < 4096; idx += 128) {
        int i = idx >> 6, j = idx & 63;
        float val = 0.f;
        if (j <= i) {
            float acc = 0.f;
            #pragma unroll 8
            for (int d = 0; d < 128; d++) {
                int dd = (d + tid) & 127;
                acc += S.x[i][dd] * S.k[j][dd];
            }
            val = acc * __expf(S.gcs[i] - S.gcs[j]);
        }
        attn_out[i * 64 + j] = val;
    }
}

// ---------------- sequential scan ----------------
#define DVS 16
struct ScanShm {
    float S[128][DVS];
    float w[64][132];
    float q[64][132];
    float k[64][132];
    float attn[64][68];
    float u[64][DVS];
    float vn[64][DVS];
    float gcs[64];
    float ex[64];
};

__global__ void __launch_bounds__(256) scan_kernel(
    const float* __restrict__ gq, const float* __restrict__ gk, const float* __restrict__ gw,
    const float* __restrict__ gu, const float* __restrict__ gattn, const float* __restrict__ ggcs,
    float* __restrict__ go) {
    ScanShm& S = *(ScanShm*)dyn_smem;
    int h = blockIdx.x;
    int dv0 = blockIdx.y * DVS;
    int tid = threadIdx.x;

    for (int idx = tid; idx < 128 * DVS; idx += 256) S.S[idx >> 4][idx & 15] = 0.f;

    for (int n = 0; n < NCHUNK; n++) {
        int base = h * T_LEN + n * 64;
        if (tid < 64) S.gcs[tid] = ggcs[base + tid];
        for (int idx = tid; idx < 64 * 128; idx += 256) {
            int i = idx >> 7, d = idx & 127;
            size_t gidx = (size_t)(base + i) * DHEAD + d;
            S.w[i][d] = gw[gidx];
            S.q[i][d] = gq[gidx];
            S.k[i][d] = gk[gidx];
        }
        const float* ap = gattn + ((size_t)(h * 64 + n)) * 64 * 64;
        for (int idx = tid; idx < 4096; idx += 256) S.attn[idx >> 6][idx & 63] = ap[idx];
        for (int idx = tid; idx < 64 * DVS; idx += 256) {
            int i = idx >> 4, dv = idx & 15;
            S.u[i][dv] = gu[(size_t)(base + i) * DHEAD + dv0 + dv];
        }
        __syncthreads();
        if (tid < 64) S.ex[tid] = __expf(S.gcs[63] - S.gcs[tid]);

        int i = tid >> 2, dvb = (tid & 3) * 4;
        {
            float4 uv = *(const float4*)&S.u[i][dvb];
            float a0 = uv.x, a1 = uv.y, a2 = uv.z, a3 = uv.w;
            for (int d = 0; d < 128; d++) {
                float wv = S.w[i][d];
                float4 sv = *(const float4*)&S.S[d][dvb];
                a0 -= wv * sv.x; a1 -= wv * sv.y; a2 -= wv * sv.z; a3 -= wv * sv.w;
            }
            float4 r; r.x = a0; r.y = a1; r.z = a2; r.w = a3;
            *(float4*)&S.vn[i][dvb] = r;
        }
        __syncthreads();
        {
            float a0 = 0, a1 = 0, a2 = 0, a3 = 0;
            for (int d = 0; d < 128; d++) {
                float qv = S.q[i][d];
                float4 sv = *(const float4*)&S.S[d][dvb];
                a0 += qv * sv.x; a1 += qv * sv.y; a2 += qv * sv.z; a3 += qv * sv.w;
            }
            float eg = __expf(S.gcs[i]);
            a0 *= eg; a1 *= eg; a2 *= eg; a3 *= eg;
            for (int j = 0; j <= i; j++) {
                float av = S.attn[i][j];
                float4 vv = *(const float4*)&S.vn[j][dvb];
                a0 += av * vv.x; a1 += av * vv.y; a2 += av * vv.z; a3 += av * vv.w;
            }
            float4 r; r.x = a0; r.y = a1; r.z = a2; r.w = a3;
            *(float4*)(go + (size_t)(base + i) * DHEAD + dv0 + dvb) = r;
        }
        __syncthreads();
        {
            float gle = __expf(S.gcs[63]);
            #pragma unroll
            for (int r = 0; r < 2; r++) {
                int qi = tid + 256 * r;
                int d = qi >> 2, db = (qi & 3) * 4;
                float4 sv = *(const float4*)&S.S[d][db];
                float a0 = sv.x * gle, a1 = sv.y * gle, a2 = sv.z * gle, a3 = sv.w * gle;
                for (int ii = 0; ii < 64; ii++) {
                    float kk = S.k[ii][d] * S.ex[ii];
                    float4 vv = *(const float4*)&S.vn[ii][db];
                    a0 += kk * vv.x; a1 += kk * vv.y; a2 += kk * vv.z; a3 += kk * vv.w;
                }
                float4 w4; w4.x = a0; w4.y = a1; w4.z = a2; w4.w = a3;
                *(float4*)&S.S[d][db] = w4;
            }
        }
        __syncthreads();
    }
}

// ---------------- gated RMSNorm * silu(z) -> fp16 ----------------
__global__ void gated_out_kernel(const float* __restrict__ go, const float* __restrict__ qkvz,
                                 const float* __restrict__ onw, __half* __restrict__ oc16) {
    int h = blockIdx.x, t = blockIdx.y, d = threadIdx.x;
    __shared__ float shm[32];
    float v = go[((size_t)h * T_LEN + t) * DHEAD + d];
    float ss = block_reduce_sum(v * v, shm, d, 128);
    float inv = rsqrtf(ss / 128.f + 1e-5f);
    float z = qkvz[(size_t)t * QKVZ_N + MIX_N + h * 128 + d];
    float res = v * inv * onw[d] * silu_f(z);
    oc16[(size_t)t * DMODEL + h * 128 + d] = __float2half(res);
}

// ---------------- GLU -> fp16 ----------------
__global__ void glu_kernel(const float* __restrict__ gate, const float* __restrict__ up,
                           __half* __restrict__ gu16) {
    int i = blockIdx.x * blockDim.x + threadIdx.x;
    float v = silu_f(gate[i]) * up[i];
    gu16[i] = __float2half(v);
}

// ---------------- host launch ----------------
extern "C" void kernel_launch(void* const* d_in, const int* in_sizes, int n_in,
                              void* d_out, int out_size) {
    const float* x       = (const float*)d_in[0];
    const float* ln1_w   = (const float*)d_in[2];
    const float* qkvz_w  = (const float*)d_in[3];
    const float* ba_w    = (const float*)d_in[4];
    const float* conv_w  = (const float*)d_in[5];
    const float* A_log   = (const float*)d_in[6];
    const float* dt_bias = (const float*)d_in[7];
    const float* o_norm_w= (const float*)d_in[8];
    const float* out_w   = (const float*)d_in[9];
    const float* ln2_w   = (const float*)d_in[10];
    const float* gate_w  = (const float*)d_in[11];
    const float* up_w    = (const float*)d_in[12];
    const float* down_w  = (const float*)d_in[13];
    float* out = (float*)d_out;

    float *h, *qkvz, *ba, *qb, *kb, *vb, *beta, *gg, *gcs, *u, *w, *attn, *o, *x2, *up;
    cudaGetSymbolAddress((void**)&h,    g_h);
    cudaGetSymbolAddress((void**)&qkvz, g_qkvz);
    cudaGetSymbolAddress((void**)&ba,   g_ba);
    cudaGetSymbolAddress((void**)&qb,   g_qb);
    cudaGetSymbolAddress((void**)&kb,   g_kb);
    cudaGetSymbolAddress((void**)&vb,   g_vb);
    cudaGetSymbolAddress((void**)&beta, g_beta);
    cudaGetSymbolAddress((void**)&gg,   g_g);
    cudaGetSymbolAddress((void**)&gcs,  g_gcs);
    cudaGetSymbolAddress((void**)&u,    g_u);
    cudaGetSymbolAddress((void**)&w,    g_wb);
    cudaGetSymbolAddress((void**)&attn, g_attn);
    cudaGetSymbolAddress((void**)&o,    g_o);
    cudaGetSymbolAddress((void**)&x2,   g_x2);
    cudaGetSymbolAddress((void**)&up,   g_up);

    __half *h16, *oc16, *gu16, *w1, *wo, *wg, *wu, *wd;
    cudaGetSymbolAddress((void**)&h16,  b_h16);
    cudaGetSymbolAddress((void**)&oc16, b_oc16);
    cudaGetSymbolAddress((void**)&gu16, b_gu16);
    cudaGetSymbolAddress((void**)&w1,   b_w1);
    cudaGetSymbolAddress((void**)&wo,   b_wo);
    cudaGetSymbolAddress((void**)&wg,   b_wg);
    cudaGetSymbolAddress((void**)&wu,   b_wu);
    cudaGetSymbolAddress((void**)&wd,   b_wd);

    cudaFuncSetAttribute(prep_kernel, cudaFuncAttributeMaxDynamicSharedMemorySize, (int)sizeof(PrepShm));
    cudaFuncSetAttribute(scan_kernel, cudaFuncAttributeMaxDynamicSharedMemorySize, (int)sizeof(ScanShm));
    const int GSMEM = 3 * GSTAGE;  // 48KB
    cudaFuncSetAttribute(gemm_tc, cudaFuncAttributeMaxDynamicSharedMemorySize, GSMEM);

    // weight conversions
    cvt16<<<(QKVZ_N * DMODEL) / 1024, 256>>>(qkvz_w, w1, QKVZ_N * DMODEL);
    cvt16<<<(DMODEL * DMODEL) / 1024, 256>>>(out_w,  wo, DMODEL * DMODEL);
    cvt16<<<(MDIM * DMODEL) / 1024, 256>>>(gate_w, wg, MDIM * DMODEL);
    cvt16<<<(MDIM * DMODEL) / 1024, 256>>>(up_w,   wu, MDIM * DMODEL);
    cvt16<<<(DMODEL * MDIM) / 1024, 256>>>(down_w, wd, DMODEL * MDIM);

    // 1) h = rms(x, ln1) (+ fp16)
    rmsnorm_kernel<<<T_LEN, 256>>>(x, ln1_w, h, h16);
    // 2) qkvz = h @ qkvz_w^T ; ba = h @ ba_w^T
    gemm_tc<<<dim3(QKVZ_N / 128, T_LEN / 128), 128, GSMEM>>>(h16, w1, (const float*)0, qkvz, T_LEN, QKVZ_N, DMODEL);
    gemm_n32<<<T_LEN / 32, 256>>>(h, ba_w, ba, DMODEL);
    // 3) conv + silu + l2norm
    conv_kernel<<<dim3(48, T_LEN), 128>>>(qkvz, conv_w, qb, kb, vb);
    // 4) beta, g, gcs
    betag_kernel<<<(NHEAD * T_LEN + 255) / 256, 256>>>(ba, A_log, dt_bias, beta, gg);
    gcs_kernel<<<NHEAD * NCHUNK, 64>>>(gg, gcs);
    // 5) chunk prep
    prep_kernel<<<dim3(NCHUNK, NHEAD), 128, sizeof(PrepShm)>>>(kb, vb, qb, beta, gcs, u, w, attn);
    // 6) scan
    scan_kernel<<<dim3(NHEAD, DHEAD / DVS), 256, sizeof(ScanShm)>>>(qb, kb, w, u, attn, gcs, o);
    // 7) gated norm * silu(z) -> oc16
    gated_out_kernel<<<dim3(NHEAD, T_LEN), 128>>>(o, qkvz, o_norm_w, oc16);
    // 8) x2 = x + oc @ out_w^T
    gemm_tc<<<dim3(DMODEL / 128, T_LEN / 128), 128, GSMEM>>>(oc16, wo, x, x2, T_LEN, DMODEL, DMODEL);
    // 9) h2 = rms(x2, ln2)
    rmsnorm_kernel<<<T_LEN, 256>>>(x2, ln2_w, h, h16);
    // 10) gate, up GEMMs
    gemm_tc<<<dim3(MDIM / 128, T_LEN / 128), 128, GSMEM>>>(h16, wg, (const float*)0, qkvz, T_LEN, MDIM, DMODEL);
    gemm_tc<<<dim3(MDIM / 128, T_LEN / 128), 128, GSMEM>>>(h16, wu, (const float*)0, up, T_LEN, MDIM, DMODEL);
    // 11) gu = silu(gate) * up -> fp16
    glu_kernel<<<(T_LEN * MDIM) / 256, 256>>>(qkvz, up, gu16);
    // 12) out = x2 + gu @ down_w^T
    gemm_tc<<<dim3(DMODEL / 128, T_LEN / 128), 128, GSMEM>>>(gu16, wd, x2, out, T_LEN, DMODEL, MDIM);
}

// round 12
// speedup vs baseline: 1.2174x; 1.2174x over previous
#include <cuda_runtime.h>
#include <cuda_fp16.h>
#include <math.h>
#include <stdint.h>

// ---------------- Problem constants (B=1) ----------------
#define T_LEN   4096
#define DMODEL  2048
#define NHEAD   16
#define DHEAD   128
#define NCHUNK  64
#define CLEN    64
#define QKVZ_N  8192
#define MIX_N   6144
#define MDIM    8192

// ---------------- fp32 scratch ----------------
__device__ float g_h   [T_LEN * DMODEL];
__device__ float g_qkvz[T_LEN * QKVZ_N];
__device__ float g_ba  [T_LEN * 32];
__device__ float g_qb  [NHEAD * T_LEN * DHEAD];
__device__ float g_kb  [NHEAD * T_LEN * DHEAD];
__device__ float g_vb  [NHEAD * T_LEN * DHEAD];
__device__ float g_beta[NHEAD * T_LEN];
__device__ float g_g   [NHEAD * T_LEN];
__device__ float g_gcs [NHEAD * T_LEN];
__device__ float g_u   [NHEAD * T_LEN * DHEAD];
__device__ float g_wb  [NHEAD * T_LEN * DHEAD];
__device__ float g_attn[NHEAD * NCHUNK * CLEN * CLEN];
__device__ float g_o   [NHEAD * T_LEN * DHEAD];
__device__ float g_x2  [T_LEN * DMODEL];
__device__ float g_up  [T_LEN * MDIM];

// ---------------- fp16 operand scratch ----------------
__device__ __half b_h16 [T_LEN * DMODEL];
__device__ __half b_oc16[T_LEN * DMODEL];
__device__ __half b_gu16[T_LEN * MDIM];
__device__ __half b_w1 [QKVZ_N * DMODEL];
__device__ __half b_wo [DMODEL * DMODEL];
__device__ __half b_wg [MDIM * DMODEL];
__device__ __half b_wu [MDIM * DMODEL];
__device__ __half b_wd [DMODEL * MDIM];

// ---------------- PTX helpers (sm_103-safe) ----------------
__device__ __forceinline__ uint32_t smem_u32(const void* p) {
    uint32_t a;
    asm("{ .reg .u64 t; cvta.to.shared.u64 t, %1; cvt.u32.u64 %0, t; }" : "=r"(a) : "l"(p));
    return a;
}
#define CP_ASYNC16(d,s) asm volatile("cp.async.cg.shared.global [%0], [%1], 16;" :: "r"(d), "l"(s))
#define CP_COMMIT()     asm volatile("cp.async.commit_group;" ::: "memory")
#define CP_WAIT2()      asm volatile("cp.async.wait_group 2;" ::: "memory")
#define CP_WAIT1()      asm volatile("cp.async.wait_group 1;" ::: "memory")
#define CP_WAIT0()      asm volatile("cp.async.wait_group 0;" ::: "memory")

__device__ __forceinline__ void ldsm4(uint32_t addr, uint32_t* o) {
    uint32_t r0, r1, r2, r3;
    asm volatile("ldmatrix.sync.aligned.m8n8.x4.shared.b16 {%0,%1,%2,%3}, [%4];"
        : "=r"(r0), "=r"(r1), "=r"(r2), "=r"(r3) : "r"(addr));
    o[0] = r0; o[1] = r1; o[2] = r2; o[3] = r3;
}

__device__ __forceinline__ void mma16816(float* d, uint32_t a0, uint32_t a1, uint32_t a2,
                                         uint32_t a3, uint32_t b0, uint32_t b1) {
    float t0 = d[0], t1 = d[1], t2 = d[2], t3 = d[3];
    asm volatile("mma.sync.aligned.m16n8k16.row.col.f32.f16.f16.f32 "
        "{%0,%1,%2,%3},{%4,%5,%6,%7},{%8,%9},{%0,%1,%2,%3};"
        : "+f"(t0), "+f"(t1), "+f"(t2), "+f"(t3)
        : "r"(a0), "r"(a1), "r"(a2), "r"(a3), "r"(b0), "r"(b1));
    d[0] = t0; d[1] = t1; d[2] = t2; d[3] = t3;
}

// ---------------- helpers ----------------
__device__ __forceinline__ float block_reduce_sum(float v, float* shm, int tid, int nthreads) {
    #pragma unroll
    for (int o = 16; o; o >>= 1) v += __shfl_down_sync(0xffffffffu, v, o);
    __syncthreads();
    if ((tid & 31) == 0) shm[tid >> 5] = v;
    __syncthreads();
    int nw = nthreads >> 5;
    float s = (tid < nw) ? shm[tid] : 0.f;
    if (tid < 32) {
        #pragma unroll
        for (int o = 16; o; o >>= 1) s += __shfl_down_sync(0xffffffffu, s, o);
        if (tid == 0) shm[0] = s;
    }
    __syncthreads();
    return shm[0];
}
__device__ __forceinline__ float silu_f(float x) { return x / (1.f + __expf(-x)); }

// ---------------- weight fp32 -> fp16 ----------------
__global__ void cvt16(const float* __restrict__ x, __half* __restrict__ y, int n) {
    int i = (blockIdx.x * blockDim.x + threadIdx.x) * 4;
    if (i >= n) return;
    float4 v = *(const float4*)(x + i);
    __half2* yp = (__half2*)(y + i);
    yp[0] = __halves2half2(__float2half(v.x), __float2half(v.y));
    yp[1] = __halves2half2(__float2half(v.z), __float2half(v.w));
}

// ---------------- RMSNorm + fp16 ----------------
__global__ void rmsnorm_kernel(const float* __restrict__ x, const float* __restrict__ w,
                               float* __restrict__ y, __half* __restrict__ y16) {
    int t = blockIdx.x, tid = threadIdx.x;
    __shared__ float shm[32];
    const float* xr = x + (size_t)t * DMODEL;
    float ss = 0.f;
    for (int d = tid; d < DMODEL; d += 256) { float v = xr[d]; ss += v * v; }
    ss = block_reduce_sum(ss, shm, tid, 256);
    float inv = rsqrtf(ss / (float)DMODEL + 1e-5f);
    for (int d = tid; d < DMODEL; d += 256) {
        float v = xr[d] * inv * w[d];
        y[(size_t)t * DMODEL + d] = v;
        y16[(size_t)t * DMODEL + d] = __float2half(v);
    }
}

// ---------------- HMMA GEMM, single fp16 term, 4-buffer / 1-sync pipeline ----------------
// C[M,N] = A@B^T (+R). 128x128 tile, BK=32, 8 warps (4x2), warp tile 32x64.
// Per stage: wait -> ONE sync -> issue loads for st+3 -> compute st.
// The sync both publishes stage-st cp.async data and frees buffer (st+3)&3 (== (st-1)&3).
#define GSTAGE 16384   // A 8K | B 8K
__global__ void __launch_bounds__(256, 2) gemm_tc(
    const __half* __restrict__ A, const __half* __restrict__ B,
    const float* __restrict__ R, float* __restrict__ C, int M, int N, int K) {
    extern __shared__ char smem_raw[];
    uint32_t sbase = smem_u32(smem_raw);
    int tid = threadIdx.x, lane = tid & 31, warp = tid >> 5;
    int wm = warp >> 1, wn = warp & 1;
    int m0 = blockIdx.y * 128, n0 = blockIdx.x * 128;
    const int TS = K >> 5;

    float acc[2][8][4];
    #pragma unroll
    for (int a = 0; a < 2; a++)
        #pragma unroll
        for (int b = 0; b < 8; b++)
            #pragma unroll
            for (int c = 0; c < 4; c++) acc[a][b][c] = 0.f;

    uint32_t aoff[2][2], boff[4][2];
    {
        int mat = lane >> 3, r = lane & 7;
        #pragma unroll
        for (int mt = 0; mt < 2; mt++) {
            int row = wm * 32 + mt * 16 + ((mat & 1) << 3) + r;
            #pragma unroll
            for (int ks = 0; ks < 2; ks++) {
                int ch = (ks << 1) + (mat >> 1);
                aoff[mt][ks] = row * 64 + ((ch ^ ((row >> 1) & 3)) << 4);
            }
        }
        #pragma unroll
        for (int j = 0; j < 4; j++) {
            int row = wn * 64 + j * 16 + ((mat >> 1) << 3) + r;
            #pragma unroll
            for (int ks = 0; ks < 2; ks++) {
                int ch = (ks << 1) + (mat & 1);
                boff[j][ks] = 8192 + row * 64 + ((ch ^ ((row >> 1) & 3)) << 4);
            }
        }
    }

    int lrow[2], lc[2]; uint32_t lso[2];
    #pragma unroll
    for (int i = 0; i < 2; i++) {
        int id = (tid << 1) | i;
        lrow[i] = id >> 2; lc[i] = id & 3;
        lso[i] = lrow[i] * 64 + ((lc[i] ^ ((lrow[i] >> 1) & 3)) << 4);
    }

    auto load_stage = [&](int st) {
        int buf = st & 3;
        int k0 = st << 5;
        uint32_t bb = sbase + buf * GSTAGE;
        #pragma unroll
        for (int i = 0; i < 2; i++) {
            CP_ASYNC16(bb + lso[i],        A + (size_t)(m0 + lrow[i]) * K + k0 + lc[i] * 8);
            CP_ASYNC16(bb + 8192 + lso[i], B + (size_t)(n0 + lrow[i]) * K + k0 + lc[i] * 8);
        }
        CP_COMMIT();
    };

    load_stage(0); load_stage(1); load_stage(2);

    for (int st = 0; st < TS; st++) {
        int rem = TS - 1 - st;
        if (rem >= 2) { CP_WAIT2(); } else if (rem == 1) { CP_WAIT1(); } else { CP_WAIT0(); }
        __syncthreads();
        if (st + 3 < TS) load_stage(st + 3);

        uint32_t stb = sbase + (st & 3) * GSTAGE;
        #pragma unroll
        for (int ks = 0; ks < 2; ks++) {
            uint32_t af[2][4], bf[4][4];
            ldsm4(stb + aoff[0][ks], af[0]);
            ldsm4(stb + aoff[1][ks], af[1]);
            #pragma unroll
            for (int j = 0; j < 4; j++) ldsm4(stb + boff[j][ks], bf[j]);
            #pragma unroll
            for (int mt = 0; mt < 2; mt++)
                #pragma unroll
                for (int j = 0; j < 4; j++) {
                    mma16816(&acc[mt][2 * j][0],     af[mt][0], af[mt][1], af[mt][2], af[mt][3], bf[j][0], bf[j][1]);
                    mma16816(&acc[mt][2 * j + 1][0], af[mt][0], af[mt][1], af[mt][2], af[mt][3], bf[j][2], bf[j][3]);
                }
        }
    }

    #pragma unroll
    for (int mt = 0; mt < 2; mt++) {
        #pragma unroll
        for (int nt = 0; nt < 8; nt++) {
            int rr = m0 + wm * 32 + mt * 16 + (lane >> 2);
            int cc = n0 + wn * 64 + nt * 8 + ((lane & 3) << 1);
            float2 v0, v1;
            v0.x = acc[mt][nt][0]; v0.y = acc[mt][nt][1];
            v1.x = acc[mt][nt][2]; v1.y = acc[mt][nt][3];
            if (R != 0) {
                const float2 r0 = *(const float2*)(R + (size_t)rr * N + cc);
                const float2 r1 = *(const float2*)(R + (size_t)(rr + 8) * N + cc);
                v0.x += r0.x; v0.y += r0.y; v1.x += r1.x; v1.y += r1.y;
            }
            *(float2*)(C + (size_t)rr * N + cc) = v0;
            *(float2*)(C + (size_t)(rr + 8) * N + cc) = v1;
        }
    }
}

// ---------------- small-N GEMM for ba ----------------
__global__ void gemm_n32(const float* __restrict__ A, const float* __restrict__ B,
                         float* __restrict__ C, int K) {
    __shared__ float hs[32][65];
    __shared__ float ws[32][65];
    int m0 = blockIdx.x * 32;
    int tid = threadIdx.x;
    int c = tid & 31, r0 = tid >> 5;
    float acc[4] = {0, 0, 0, 0};
    for (int k0 = 0; k0 < K; k0 += 64) {
        __syncthreads();
        for (int idx = tid; idx < 2048; idx += 256) {
            int r = idx >> 6, kk = idx & 63;
            hs[r][kk] = A[(size_t)(m0 + r) * K + k0 + kk];
            ws[r][kk] = B[(size_t)r * K + k0 + kk];
        }
        __syncthreads();
        for (int kk = 0; kk < 64; kk++) {
            float wv = ws[c][kk];
            #pragma unroll
            for (int s = 0; s < 4; s++) acc[s] += hs[r0 + 8 * s][kk] * wv;
        }
    }
    #pragma unroll
    for (int s = 0; s < 4; s++) C[(size_t)(m0 + r0 + 8 * s) * 32 + c] = acc[s];
}

// ---------------- causal conv + silu + l2norm + head split ----------------
__global__ void conv_kernel(const float* __restrict__ qkvz, const float* __restrict__ conv_w,
                            float* __restrict__ qo, float* __restrict__ ko, float* __restrict__ vo) {
    int t = blockIdx.y;
    int wh = blockIdx.x;
    int which = wh >> 4, head = wh & 15;
    int d = threadIdx.x;
    int c = which * 2048 + head * 128 + d;
    float acc = 0.f;
    #pragma unroll
    for (int j = 0; j < 4; j++) {
        int tt = t - 3 + j;
        if (tt >= 0) acc += qkvz[(size_t)tt * QKVZ_N + c] * conv_w[c * 4 + j];
    }
    float s = silu_f(acc);
    size_t oidx = ((size_t)head * T_LEN + t) * DHEAD + d;
    if (which == 2) { vo[oidx] = s; return; }
    __shared__ float shm[32];
    float ss = block_reduce_sum(s * s, shm, d, 128);
    float val = s * rsqrtf(ss + 1e-6f);
    if (which == 0) val *= 0.08838834764831845f;
    (which == 0 ? qo : ko)[oidx] = val;
}

// ---------------- beta / g ----------------
__global__ void betag_kernel(const float* __restrict__ ba, const float* __restrict__ A_log,
                             const float* __restrict__ dt_bias,
                             float* __restrict__ beta, float* __restrict__ g) {
    int idx = blockIdx.x * blockDim.x + threadIdx.x;
    if (idx >= NHEAD * T_LEN) return;
    int t = idx >> 4, h = idx & 15;
    float b = ba[t * 32 + h];
    float a = ba[t * 32 + 16 + h];
    beta[h * T_LEN + t] = 1.f / (1.f + expf(-b));
    float xx = a + dt_bias[h];
    float sp = (xx > 20.f) ? xx : log1pf(expf(xx));
    g[h * T_LEN + t] = -expf(A_log[h]) * sp;
}

// ---------------- within-chunk cumsum of g ----------------
__global__ void gcs_kernel(const float* __restrict__ g, float* __restrict__ gcs) {
    int h = blockIdx.x >> 6, n = blockIdx.x & 63;
    __shared__ float s[64];
    int i = threadIdx.x;
    int base = h * T_LEN + n * 64;
    s[i] = g[base + i];
    __syncthreads();
    for (int off = 1; off < 64; off <<= 1) {
        float v = (i >= off) ? s[i - off] : 0.f;
        __syncthreads();
        s[i] += v;
        __syncthreads();
    }
    gcs[base + i] = s[i];
}

// ---------------- per-chunk prep: A, T=(I+A)^-1, u, w, attn ----------------
struct PrepShm {
    float k[64][128];
    float x[64][128];
    float A[64][64];
    float T[64][64];
    float gcs[64];
    float beta[64];
    float coef[64];
};
extern __shared__ float dyn_smem[];

__global__ void __launch_bounds__(128) prep_kernel(
    const float* __restrict__ gk, const float* __restrict__ gv, const float* __restrict__ gq,
    const float* __restrict__ gbeta, const float* __restrict__ ggcs,
    float* __restrict__ gu, float* __restrict__ gw, float* __restrict__ gattn) {
    PrepShm& S = *(PrepShm*)dyn_smem;
    int n = blockIdx.x, h = blockIdx.y;
    int tid = threadIdx.x;
    int base = h * T_LEN + n * 64;

    if (tid < 64) {
        S.gcs[tid]  = ggcs[base + tid];
        S.beta[tid] = gbeta[base + tid];
    }
    for (int idx = tid; idx < 64 * 128; idx += 128) {
        int i = idx >> 7, d = idx & 127;
        S.k[i][d] = gk[(size_t)(base + i) * DHEAD + d];
    }
    __syncthreads();
    for (int idx = tid; idx < 64 * 128; idx += 128) {
        int i = idx >> 7, d = idx & 127;
        S.x[i][d] = gv[(size_t)(base + i) * DHEAD + d] * S.beta[i];
    }
    for (int idx = tid; idx < 4096; idx += 128) {
        int i = idx >> 6, j = idx & 63;
        float val = 0.f;
        if (j < i) {
            float acc = 0.f;
            #pragma unroll 8
            for (int d = 0; d < 128; d++) {
                int dd = (d + tid) & 127;
                acc += S.k[i][dd] * S.k[j][dd];
            }
            val = acc * S.beta[i] * __expf(S.gcs[i] - S.gcs[j]);
        }
        S.A[i][j] = val;
    }
    __syncthreads();
    if (tid < 64) S.T[0][tid] = (tid == 0) ? 1.f : 0.f;
    __syncthreads();
    for (int i = 1; i < 64; i++) {
        if (tid < 64) {
            float acc = 0.f;
            for (int j = 0; j < i; j++) acc += S.A[i][j] * S.T[j][tid];
            S.T[i][tid] = ((tid == i) ? 1.f : 0.f) - acc;
        }
        __syncthreads();
    }
    if (tid < 64) S.coef[tid] = S.beta[tid] * __expf(S.gcs[tid]);
    __syncthreads();
    for (int idx = tid; idx < 64 * 128; idx += 128) {
        int i = idx >> 7, d = idx & 127;
        float au = 0.f, aw = 0.f;
        for (int j = 0; j <= i; j++) {
            float tij = S.T[i][j];
            au += tij * S.x[j][d];
            aw += tij * S.coef[j] * S.k[j][d];
        }
        gu[(size_t)(base + i) * DHEAD + d] = au;
        gw[(size_t)(base + i) * DHEAD + d] = aw;
    }
    __syncthreads();
    for (int idx = tid; idx < 64 * 128; idx += 128) {
        int i = idx >> 7, d = idx & 127;
        S.x[i][d] = gq[(size_t)(base + i) * DHEAD + d];
    }
    __syncthreads();
    float* attn_out = gattn + ((size_t)(h * 64 + n)) * 64 * 64;
    for (int idx = tid; idx < 4096; idx += 128) {
        int i = idx >> 6, j = idx & 63;
        float val = 0.f;
        if (j <= i) {
            float acc = 0.f;
            #pragma unroll 8
            for (int d = 0; d < 128; d++) {
                int dd = (d + tid) & 127;
                acc += S.x[i][dd] * S.k[j][dd];
            }
            val = acc * __expf(S.gcs[i] - S.gcs[j]);
        }
        attn_out[i * 64 + j] = val;
    }
}

// ---------------- sequential scan ----------------
#define DVS 16
struct ScanShm {
    float S[128][DVS];
    float w[64][132];
    float q[64][132];
    float k[64][132];
    float attn[64][68];
    float u[64][DVS];
    float vn[64][DVS];
    float gcs[64];
    float ex[64];
};

__global__ void __launch_bounds__(256) scan_kernel(
    const float* __restrict__ gq, const float* __restrict__ gk, const float* __restrict__ gw,
    const float* __restrict__ gu, const float* __restrict__ gattn, const float* __restrict__ ggcs,
    float* __restrict__ go) {
    ScanShm& S = *(ScanShm*)dyn_smem;
    int h = blockIdx.x;
    int dv0 = blockIdx.y * DVS;
    int tid = threadIdx.x;

    for (int idx = tid; idx < 128 * DVS; idx += 256) S.S[idx >> 4][idx & 15] = 0.f;

    for (int n = 0; n < NCHUNK; n++) {
        int base = h * T_LEN + n * 64;
        if (tid < 64) S.gcs[tid] = ggcs[base + tid];
        for (int idx = tid; idx < 64 * 128; idx += 256) {
            int i = idx >> 7, d = idx & 127;
            size_t gidx = (size_t)(base + i) * DHEAD + d;
            S.w[i][d] = gw[gidx];
            S.q[i][d] = gq[gidx];
            S.k[i][d] = gk[gidx];
        }
        const float* ap = gattn + ((size_t)(h * 64 + n)) * 64 * 64;
        for (int idx = tid; idx < 4096; idx += 256) S.attn[idx >> 6][idx & 63] = ap[idx];
        for (int idx = tid; idx < 64 * DVS; idx += 256) {
            int i = idx >> 4, dv = idx & 15;
            S.u[i][dv] = gu[(size_t)(base + i) * DHEAD + dv0 + dv];
        }
        __syncthreads();
        if (tid < 64) S.ex[tid] = __expf(S.gcs[63] - S.gcs[tid]);

        int i = tid >> 2, dvb = (tid & 3) * 4;
        {
            float4 uv = *(const float4*)&S.u[i][dvb];
            float a0 = uv.x, a1 = uv.y, a2 = uv.z, a3 = uv.w;
            for (int d = 0; d < 128; d++) {
                float wv = S.w[i][d];
                float4 sv = *(const float4*)&S.S[d][dvb];
                a0 -= wv * sv.x; a1 -= wv * sv.y; a2 -= wv * sv.z; a3 -= wv * sv.w;
            }
            float4 r; r.x = a0; r.y = a1; r.z = a2; r.w = a3;
            *(float4*)&S.vn[i][dvb] = r;
        }
        __syncthreads();
        {
            float a0 = 0, a1 = 0, a2 = 0, a3 = 0;
            for (int d = 0; d < 128; d++) {
                float qv = S.q[i][d];
                float4 sv = *(const float4*)&S.S[d][dvb];
                a0 += qv * sv.x; a1 += qv * sv.y; a2 += qv * sv.z; a3 += qv * sv.w;
            }
            float eg = __expf(S.gcs[i]);
            a0 *= eg; a1 *= eg; a2 *= eg; a3 *= eg;
            for (int j = 0; j <= i; j++) {
                float av = S.attn[i][j];
                float4 vv = *(const float4*)&S.vn[j][dvb];
                a0 += av * vv.x; a1 += av * vv.y; a2 += av * vv.z; a3 += av * vv.w;
            }
            float4 r; r.x = a0; r.y = a1; r.z = a2; r.w = a3;
            *(float4*)(go + (size_t)(base + i) * DHEAD + dv0 + dvb) = r;
        }
        __syncthreads();
        {
            float gle = __expf(S.gcs[63]);
            #pragma unroll
            for (int r = 0; r < 2; r++) {
                int qi = tid + 256 * r;
                int d = qi >> 2, db = (qi & 3) * 4;
                float4 sv = *(const float4*)&S.S[d][db];
                float a0 = sv.x * gle, a1 = sv.y * gle, a2 = sv.z * gle, a3 = sv.w * gle;
                for (int ii = 0; ii < 64; ii++) {
                    float kk = S.k[ii][d] * S.ex[ii];
                    float4 vv = *(const float4*)&S.vn[ii][db];
                    a0 += kk * vv.x; a1 += kk * vv.y; a2 += kk * vv.z; a3 += kk * vv.w;
                }
                float4 w4; w4.x = a0; w4.y = a1; w4.z = a2; w4.w = a3;
                *(float4*)&S.S[d][db] = w4;
            }
        }
        __syncthreads();
    }
}

// ---------------- gated RMSNorm * silu(z) -> fp16 ----------------
__global__ void gated_out_kernel(const float* __restrict__ go, const float* __restrict__ qkvz,
                                 const float* __restrict__ onw, __half* __restrict__ oc16) {
    int h = blockIdx.x, t = blockIdx.y, d = threadIdx.x;
    __shared__ float shm[32];
    float v = go[((size_t)h * T_LEN + t) * DHEAD + d];
    float ss = block_reduce_sum(v * v, shm, d, 128);
    float inv = rsqrtf(ss / 128.f + 1e-5f);
    float z = qkvz[(size_t)t * QKVZ_N + MIX_N + h * 128 + d];
    float res = v * inv * onw[d] * silu_f(z);
    oc16[(size_t)t * DMODEL + h * 128 + d] = __float2half(res);
}

// ---------------- GLU -> fp16 ----------------
__global__ void glu_kernel(const float* __restrict__ gate, const float* __restrict__ up,
                           __half* __restrict__ gu16) {
    int i = blockIdx.x * blockDim.x + threadIdx.x;
    float v = silu_f(gate[i]) * up[i];
    gu16[i] = __float2half(v);
}

// ---------------- host launch ----------------
extern "C" void kernel_launch(void* const* d_in, const int* in_sizes, int n_in,
                              void* d_out, int out_size) {
    const float* x       = (const float*)d_in[0];
    const float* ln1_w   = (const float*)d_in[2];
    const float* qkvz_w  = (const float*)d_in[3];
    const float* ba_w    = (const float*)d_in[4];
    const float* conv_w  = (const float*)d_in[5];
    const float* A_log   = (const float*)d_in[6];
    const float* dt_bias = (const float*)d_in[7];
    const float* o_norm_w= (const float*)d_in[8];
    const float* out_w   = (const float*)d_in[9];
    const float* ln2_w   = (const float*)d_in[10];
    const float* gate_w  = (const float*)d_in[11];
    const float* up_w    = (const float*)d_in[12];
    const float* down_w  = (const float*)d_in[13];
    float* out = (float*)d_out;

    float *h, *qkvz, *ba, *qb, *kb, *vb, *beta, *gg, *gcs, *u, *w, *attn, *o, *x2, *up;
    cudaGetSymbolAddress((void**)&h,    g_h);
    cudaGetSymbolAddress((void**)&qkvz, g_qkvz);
    cudaGetSymbolAddress((void**)&ba,   g_ba);
    cudaGetSymbolAddress((void**)&qb,   g_qb);
    cudaGetSymbolAddress((void**)&kb,   g_kb);
    cudaGetSymbolAddress((void**)&vb,   g_vb);
    cudaGetSymbolAddress((void**)&beta, g_beta);
    cudaGetSymbolAddress((void**)&gg,   g_g);
    cudaGetSymbolAddress((void**)&gcs,  g_gcs);
    cudaGetSymbolAddress((void**)&u,    g_u);
    cudaGetSymbolAddress((void**)&w,    g_wb);
    cudaGetSymbolAddress((void**)&attn, g_attn);
    cudaGetSymbolAddress((void**)&o,    g_o);
    cudaGetSymbolAddress((void**)&x2,   g_x2);
    cudaGetSymbolAddress((void**)&up,   g_up);

    __half *h16, *oc16, *gu16, *w1, *wo, *wg, *wu, *wd;
    cudaGetSymbolAddress((void**)&h16,  b_h16);
    cudaGetSymbolAddress((void**)&oc16, b_oc16);
    cudaGetSymbolAddress((void**)&gu16, b_gu16);
    cudaGetSymbolAddress((void**)&w1,   b_w1);
    cudaGetSymbolAddress((void**)&wo,   b_wo);
    cudaGetSymbolAddress((void**)&wg,   b_wg);
    cudaGetSymbolAddress((void**)&wu,   b_wu);
    cudaGetSymbolAddress((void**)&wd,   b_wd);

    cudaFuncSetAttribute(prep_kernel, cudaFuncAttributeMaxDynamicSharedMemorySize, (int)sizeof(PrepShm));
    cudaFuncSetAttribute(scan_kernel, cudaFuncAttributeMaxDynamicSharedMemorySize, (int)sizeof(ScanShm));
    const int GSMEM = 4 * GSTAGE;  // 64KB -> 2 CTAs/SM
    cudaFuncSetAttribute(gemm_tc, cudaFuncAttributeMaxDynamicSharedMemorySize, GSMEM);

    // weight conversions
    cvt16<<<(QKVZ_N * DMODEL) / 1024, 256>>>(qkvz_w, w1, QKVZ_N * DMODEL);
    cvt16<<<(DMODEL * DMODEL) / 1024, 256>>>(out_w,  wo, DMODEL * DMODEL);
    cvt16<<<(MDIM * DMODEL) / 1024, 256>>>(gate_w, wg, MDIM * DMODEL);
    cvt16<<<(MDIM * DMODEL) / 1024, 256>>>(up_w,   wu, MDIM * DMODEL);
    cvt16<<<(DMODEL * MDIM) / 1024, 256>>>(down_w, wd, DMODEL * MDIM);

    // 1) h = rms(x, ln1) (+ fp16)
    rmsnorm_kernel<<<T_LEN, 256>>>(x, ln1_w, h, h16);
    // 2) qkvz = h @ qkvz_w^T ; ba = h @ ba_w^T
    gemm_tc<<<dim3(QKVZ_N / 128, T_LEN / 128), 256, GSMEM>>>(h16, w1, (const float*)0, qkvz, T_LEN, QKVZ_N, DMODEL);
    gemm_n32<<<T_LEN / 32, 256>>>(h, ba_w, ba, DMODEL);
    // 3) conv + silu + l2norm
    conv_kernel<<<dim3(48, T_LEN), 128>>>(qkvz, conv_w, qb, kb, vb);
    // 4) beta, g, gcs
    betag_kernel<<<(NHEAD * T_LEN + 255) / 256, 256>>>(ba, A_log, dt_bias, beta, gg);
    gcs_kernel<<<NHEAD * NCHUNK, 64>>>(gg, gcs);
    // 5) chunk prep
    prep_kernel<<<dim3(NCHUNK, NHEAD), 128, sizeof(PrepShm)>>>(kb, vb, qb, beta, gcs, u, w, attn);
    // 6) scan
    scan_kernel<<<dim3(NHEAD, DHEAD / DVS), 256, sizeof(ScanShm)>>>(qb, kb, w, u, attn, gcs, o);
    // 7) gated norm * silu(z) -> oc16
    gated_out_kernel<<<dim3(NHEAD, T_LEN), 128>>>(o, qkvz, o_norm_w, oc16);
    // 8) x2 = x + oc @ out_w^T
    gemm_tc<<<dim3(DMODEL / 128, T_LEN / 128), 256, GSMEM>>>(oc16, wo, x, x2, T_LEN, DMODEL, DMODEL);
    // 9) h2 = rms(x2, ln2)
    rmsnorm_kernel<<<T_LEN, 256>>>(x2, ln2_w, h, h16);
    // 10) gate, up GEMMs
    gemm_tc<<<dim3(MDIM / 128, T_LEN / 128), 256, GSMEM>>>(h16, wg, (const float*)0, qkvz, T_LEN, MDIM, DMODEL);
    gemm_tc<<<dim3(MDIM / 128, T_LEN / 128), 256, GSMEM>>>(h16, wu, (const float*)0, up, T_LEN, MDIM, DMODEL);
    // 11) gu = silu(gate) * up -> fp16
    glu_kernel<<<(T_LEN * MDIM) / 256, 256>>>(qkvz, up, gu16);
    // 12) out = x2 + gu @ down_w^T
    gemm_tc<<<dim3(DMODEL / 128, T_LEN / 128), 256, GSMEM>>>(gu16, wd, x2, out, T_LEN, DMODEL, MDIM);
}

// round 13
// speedup vs baseline: 1.2461x; 1.0236x over previous
#include <cuda_runtime.h>
#include <cuda_fp16.h>
#include <math.h>
#include <stdint.h>

// ---------------- Problem constants (B=1) ----------------
#define T_LEN   4096
#define DMODEL  2048
#define NHEAD   16
#define DHEAD   128
#define NCHUNK  64
#define CLEN    64
#define QKVZ_N  8192
#define MIX_N   6144
#define MDIM    8192

// ---------------- fp32 scratch ----------------
__device__ float g_h   [T_LEN * DMODEL];
__device__ float g_qkvz[T_LEN * QKVZ_N];
__device__ float g_ba  [T_LEN * 32];
__device__ float g_qb  [NHEAD * T_LEN * DHEAD];
__device__ float g_kb  [NHEAD * T_LEN * DHEAD];
__device__ float g_vb  [NHEAD * T_LEN * DHEAD];
__device__ float g_beta[NHEAD * T_LEN];
__device__ float g_g   [NHEAD * T_LEN];
__device__ float g_gcs [NHEAD * T_LEN];
__device__ float g_u   [NHEAD * T_LEN * DHEAD];
__device__ float g_wb  [NHEAD * T_LEN * DHEAD];
__device__ float g_attn[NHEAD * NCHUNK * CLEN * CLEN];
__device__ float g_o   [NHEAD * T_LEN * DHEAD];
__device__ float g_x2  [T_LEN * DMODEL];

// ---------------- fp16 operand scratch ----------------
__device__ __half b_h16   [T_LEN * DMODEL];
__device__ __half b_oc16  [T_LEN * DMODEL];
__device__ __half b_qkvz16[T_LEN * QKVZ_N];   // fp16 copy of qkvz (conv input)
__device__ __half b_gu16  [T_LEN * MDIM];     // gate (then silu(gate)*up in place)
__device__ __half b_up16  [T_LEN * MDIM];
__device__ __half b_w1 [QKVZ_N * DMODEL];
__device__ __half b_wo [DMODEL * DMODEL];
__device__ __half b_wg [MDIM * DMODEL];
__device__ __half b_wu [MDIM * DMODEL];
__device__ __half b_wd [DMODEL * MDIM];

// ---------------- PTX helpers (sm_103-safe) ----------------
__device__ __forceinline__ uint32_t smem_u32(const void* p) {
    uint32_t a;
    asm("{ .reg .u64 t; cvta.to.shared.u64 t, %1; cvt.u32.u64 %0, t; }" : "=r"(a) : "l"(p));
    return a;
}
#define CP_ASYNC16(d,s) asm volatile("cp.async.cg.shared.global [%0], [%1], 16;" :: "r"(d), "l"(s))
#define CP_COMMIT()     asm volatile("cp.async.commit_group;" ::: "memory")
#define CP_WAIT2()      asm volatile("cp.async.wait_group 2;" ::: "memory")
#define CP_WAIT1()      asm volatile("cp.async.wait_group 1;" ::: "memory")
#define CP_WAIT0()      asm volatile("cp.async.wait_group 0;" ::: "memory")

__device__ __forceinline__ void ldsm4(uint32_t addr, uint32_t* o) {
    uint32_t r0, r1, r2, r3;
    asm volatile("ldmatrix.sync.aligned.m8n8.x4.shared.b16 {%0,%1,%2,%3}, [%4];"
        : "=r"(r0), "=r"(r1), "=r"(r2), "=r"(r3) : "r"(addr));
    o[0] = r0; o[1] = r1; o[2] = r2; o[3] = r3;
}

__device__ __forceinline__ void mma16816(float* d, uint32_t a0, uint32_t a1, uint32_t a2,
                                         uint32_t a3, uint32_t b0, uint32_t b1) {
    float t0 = d[0], t1 = d[1], t2 = d[2], t3 = d[3];
    asm volatile("mma.sync.aligned.m16n8k16.row.col.f32.f16.f16.f32 "
        "{%0,%1,%2,%3},{%4,%5,%6,%7},{%8,%9},{%0,%1,%2,%3};"
        : "+f"(t0), "+f"(t1), "+f"(t2), "+f"(t3)
        : "r"(a0), "r"(a1), "r"(a2), "r"(a3), "r"(b0), "r"(b1));
    d[0] = t0; d[1] = t1; d[2] = t2; d[3] = t3;
}

// ---------------- helpers ----------------
__device__ __forceinline__ float block_reduce_sum(float v, float* shm, int tid, int nthreads) {
    #pragma unroll
    for (int o = 16; o; o >>= 1) v += __shfl_down_sync(0xffffffffu, v, o);
    __syncthreads();
    if ((tid & 31) == 0) shm[tid >> 5] = v;
    __syncthreads();
    int nw = nthreads >> 5;
    float s = (tid < nw) ? shm[tid] : 0.f;
    if (tid < 32) {
        #pragma unroll
        for (int o = 16; o; o >>= 1) s += __shfl_down_sync(0xffffffffu, s, o);
        if (tid == 0) shm[0] = s;
    }
    __syncthreads();
    return shm[0];
}
__device__ __forceinline__ float silu_f(float x) { return x / (1.f + __expf(-x)); }

// ---------------- weight fp32 -> fp16 ----------------
__global__ void cvt16(const float* __restrict__ x, __half* __restrict__ y, int n) {
    int i = (blockIdx.x * blockDim.x + threadIdx.x) * 4;
    if (i >= n) return;
    float4 v = *(const float4*)(x + i);
    __half2* yp = (__half2*)(y + i);
    yp[0] = __halves2half2(__float2half(v.x), __float2half(v.y));
    yp[1] = __halves2half2(__float2half(v.z), __float2half(v.w));
}

// ---------------- RMSNorm + fp16 ----------------
__global__ void rmsnorm_kernel(const float* __restrict__ x, const float* __restrict__ w,
                               float* __restrict__ y, __half* __restrict__ y16) {
    int t = blockIdx.x, tid = threadIdx.x;
    __shared__ float shm[32];
    const float* xr = x + (size_t)t * DMODEL;
    float ss = 0.f;
    for (int d = tid; d < DMODEL; d += 256) { float v = xr[d]; ss += v * v; }
    ss = block_reduce_sum(ss, shm, tid, 256);
    float inv = rsqrtf(ss / (float)DMODEL + 1e-5f);
    for (int d = tid; d < DMODEL; d += 256) {
        float v = xr[d] * inv * w[d];
        y[(size_t)t * DMODEL + d] = v;
        y16[(size_t)t * DMODEL + d] = __float2half(v);
    }
}

// ---------------- HMMA GEMM, 4-buffer / 1-sync pipeline ----------------
// 128x128 tile, BK=32, 8 warps (4x2), warp tile 32x64, 2 CTAs/SM.
// Outputs: fp32 C (optional, +R residual) and/or fp16 H.
#define GSTAGE 16384   // A 8K | B 8K
__global__ void __launch_bounds__(256, 2) gemm_tc(
    const __half* __restrict__ A, const __half* __restrict__ B,
    const float* __restrict__ R, float* __restrict__ C, __half* __restrict__ H,
    int M, int N, int K) {
    extern __shared__ char smem_raw[];
    uint32_t sbase = smem_u32(smem_raw);
    int tid = threadIdx.x, lane = tid & 31, warp = tid >> 5;
    int wm = warp >> 1, wn = warp & 1;
    int m0 = blockIdx.y * 128, n0 = blockIdx.x * 128;
    const int TS = K >> 5;

    float acc[2][8][4];
    #pragma unroll
    for (int a = 0; a < 2; a++)
        #pragma unroll
        for (int b = 0; b < 8; b++)
            #pragma unroll
            for (int c = 0; c < 4; c++) acc[a][b][c] = 0.f;

    uint32_t aoff[2][2], boff[4][2];
    {
        int mat = lane >> 3, r = lane & 7;
        #pragma unroll
        for (int mt = 0; mt < 2; mt++) {
            int row = wm * 32 + mt * 16 + ((mat & 1) << 3) + r;
            #pragma unroll
            for (int ks = 0; ks < 2; ks++) {
                int ch = (ks << 1) + (mat >> 1);
                aoff[mt][ks] = row * 64 + ((ch ^ ((row >> 1) & 3)) << 4);
            }
        }
        #pragma unroll
        for (int j = 0; j < 4; j++) {
            int row = wn * 64 + j * 16 + ((mat >> 1) << 3) + r;
            #pragma unroll
            for (int ks = 0; ks < 2; ks++) {
                int ch = (ks << 1) + (mat & 1);
                boff[j][ks] = 8192 + row * 64 + ((ch ^ ((row >> 1) & 3)) << 4);
            }
        }
    }

    int lrow[2], lc[2]; uint32_t lso[2];
    #pragma unroll
    for (int i = 0; i < 2; i++) {
        int id = (tid << 1) | i;
        lrow[i] = id >> 2; lc[i] = id & 3;
        lso[i] = lrow[i] * 64 + ((lc[i] ^ ((lrow[i] >> 1) & 3)) << 4);
    }

    auto load_stage = [&](int st) {
        int buf = st & 3;
        int k0 = st << 5;
        uint32_t bb = sbase + buf * GSTAGE;
        #pragma unroll
        for (int i = 0; i < 2; i++) {
            CP_ASYNC16(bb + lso[i],        A + (size_t)(m0 + lrow[i]) * K + k0 + lc[i] * 8);
            CP_ASYNC16(bb + 8192 + lso[i], B + (size_t)(n0 + lrow[i]) * K + k0 + lc[i] * 8);
        }
        CP_COMMIT();
    };

    load_stage(0); load_stage(1); load_stage(2);

    for (int st = 0; st < TS; st++) {
        int rem = TS - 1 - st;
        if (rem >= 2) { CP_WAIT2(); } else if (rem == 1) { CP_WAIT1(); } else { CP_WAIT0(); }
        __syncthreads();
        if (st + 3 < TS) load_stage(st + 3);

        uint32_t stb = sbase + (st & 3) * GSTAGE;
        #pragma unroll
        for (int ks = 0; ks < 2; ks++) {
            uint32_t af[2][4], bf[4][4];
            ldsm4(stb + aoff[0][ks], af[0]);
            ldsm4(stb + aoff[1][ks], af[1]);
            #pragma unroll
            for (int j = 0; j < 4; j++) ldsm4(stb + boff[j][ks], bf[j]);
            #pragma unroll
            for (int mt = 0; mt < 2; mt++)
                #pragma unroll
                for (int j = 0; j < 4; j++) {
                    mma16816(&acc[mt][2 * j][0],     af[mt][0], af[mt][1], af[mt][2], af[mt][3], bf[j][0], bf[j][1]);
                    mma16816(&acc[mt][2 * j + 1][0], af[mt][0], af[mt][1], af[mt][2], af[mt][3], bf[j][2], bf[j][3]);
                }
        }
    }

    #pragma unroll
    for (int mt = 0; mt < 2; mt++) {
        #pragma unroll
        for (int nt = 0; nt < 8; nt++) {
            int rr = m0 + wm * 32 + mt * 16 + (lane >> 2);
            int cc = n0 + wn * 64 + nt * 8 + ((lane & 3) << 1);
            float2 v0, v1;
            v0.x = acc[mt][nt][0]; v0.y = acc[mt][nt][1];
            v1.x = acc[mt][nt][2]; v1.y = acc[mt][nt][3];
            if (R != 0) {
                const float2 r0 = *(const float2*)(R + (size_t)rr * N + cc);
                const float2 r1 = *(const float2*)(R + (size_t)(rr + 8) * N + cc);
                v0.x += r0.x; v0.y += r0.y; v1.x += r1.x; v1.y += r1.y;
            }
            if (C != 0) {
                *(float2*)(C + (size_t)rr * N + cc) = v0;
                *(float2*)(C + (size_t)(rr + 8) * N + cc) = v1;
            }
            if (H != 0) {
                *(__half2*)(H + (size_t)rr * N + cc) = __halves2half2(__float2half(v0.x), __float2half(v0.y));
                *(__half2*)(H + (size_t)(rr + 8) * N + cc) = __halves2half2(__float2half(v1.x), __float2half(v1.y));
            }
        }
    }
}

// ---------------- small-N GEMM for ba ----------------
__global__ void gemm_n32(const float* __restrict__ A, const float* __restrict__ B,
                         float* __restrict__ C, int K) {
    __shared__ float hs[32][65];
    __shared__ float ws[32][65];
    int m0 = blockIdx.x * 32;
    int tid = threadIdx.x;
    int c = tid & 31, r0 = tid >> 5;
    float acc[4] = {0, 0, 0, 0};
    for (int k0 = 0; k0 < K; k0 += 64) {
        __syncthreads();
        for (int idx = tid; idx < 2048; idx += 256) {
            int r = idx >> 6, kk = idx & 63;
            hs[r][kk] = A[(size_t)(m0 + r) * K + k0 + kk];
            ws[r][kk] = B[(size_t)r * K + k0 + kk];
        }
        __syncthreads();
        for (int kk = 0; kk < 64; kk++) {
            float wv = ws[c][kk];
            #pragma unroll
            for (int s = 0; s < 4; s++) acc[s] += hs[r0 + 8 * s][kk] * wv;
        }
    }
    #pragma unroll
    for (int s = 0; s < 4; s++) C[(size_t)(m0 + r0 + 8 * s) * 32 + c] = acc[s];
}

// ---------------- causal conv + silu + l2norm + head split (fp16 input) ----------------
__global__ void conv_kernel(const __half* __restrict__ qkvz16, const float* __restrict__ conv_w,
                            float* __restrict__ qo, float* __restrict__ ko, float* __restrict__ vo) {
    int t = blockIdx.y;
    int wh = blockIdx.x;
    int which = wh >> 4, head = wh & 15;
    int d = threadIdx.x;
    int c = which * 2048 + head * 128 + d;
    float acc = 0.f;
    #pragma unroll
    for (int j = 0; j < 4; j++) {
        int tt = t - 3 + j;
        if (tt >= 0) acc += __half2float(qkvz16[(size_t)tt * QKVZ_N + c]) * conv_w[c * 4 + j];
    }
    float s = silu_f(acc);
    size_t oidx = ((size_t)head * T_LEN + t) * DHEAD + d;
    if (which == 2) { vo[oidx] = s; return; }
    __shared__ float shm[32];
    float ss = block_reduce_sum(s * s, shm, d, 128);
    float val = s * rsqrtf(ss + 1e-6f);
    if (which == 0) val *= 0.08838834764831845f;
    (which == 0 ? qo : ko)[oidx] = val;
}

// ---------------- beta / g ----------------
__global__ void betag_kernel(const float* __restrict__ ba, const float* __restrict__ A_log,
                             const float* __restrict__ dt_bias,
                             float* __restrict__ beta, float* __restrict__ g) {
    int idx = blockIdx.x * blockDim.x + threadIdx.x;
    if (idx >= NHEAD * T_LEN) return;
    int t = idx >> 4, h = idx & 15;
    float b = ba[t * 32 + h];
    float a = ba[t * 32 + 16 + h];
    beta[h * T_LEN + t] = 1.f / (1.f + expf(-b));
    float xx = a + dt_bias[h];
    float sp = (xx > 20.f) ? xx : log1pf(expf(xx));
    g[h * T_LEN + t] = -expf(A_log[h]) * sp;
}

// ---------------- within-chunk cumsum of g ----------------
__global__ void gcs_kernel(const float* __restrict__ g, float* __restrict__ gcs) {
    int h = blockIdx.x >> 6, n = blockIdx.x & 63;
    __shared__ float s[64];
    int i = threadIdx.x;
    int base = h * T_LEN + n * 64;
    s[i] = g[base + i];
    __syncthreads();
    for (int off = 1; off < 64; off <<= 1) {
        float v = (i >= off) ? s[i - off] : 0.f;
        __syncthreads();
        s[i] += v;
        __syncthreads();
    }
    gcs[base + i] = s[i];
}

// ---------------- per-chunk prep: A, T=(I+A)^-1, u, w, attn ----------------
struct PrepShm {
    float k[64][128];
    float x[64][128];
    float A[64][64];
    float T[64][64];
    float gcs[64];
    float beta[64];
    float coef[64];
};
extern __shared__ float dyn_smem[];

__global__ void __launch_bounds__(128) prep_kernel(
    const float* __restrict__ gk, const float* __restrict__ gv, const float* __restrict__ gq,
    const float* __restrict__ gbeta, const float* __restrict__ ggcs,
    float* __restrict__ gu, float* __restrict__ gw, float* __restrict__ gattn) {
    PrepShm& S = *(PrepShm*)dyn_smem;
    int n = blockIdx.x, h = blockIdx.y;
    int tid = threadIdx.x;
    int base = h * T_LEN + n * 64;

    if (tid < 64) {
        S.gcs[tid]  = ggcs[base + tid];
        S.beta[tid] = gbeta[base + tid];
    }
    for (int idx = tid; idx < 64 * 128; idx += 128) {
        int i = idx >> 7, d = idx & 127;
        S.k[i][d] = gk[(size_t)(base + i) * DHEAD + d];
    }
    __syncthreads();
    for (int idx = tid; idx < 64 * 128; idx += 128) {
        int i = idx >> 7, d = idx & 127;
        S.x[i][d] = gv[(size_t)(base + i) * DHEAD + d] * S.beta[i];
    }
    for (int idx = tid; idx < 4096; idx += 128) {
        int i = idx >> 6, j = idx & 63;
        float val = 0.f;
        if (j < i) {
            float acc = 0.f;
            #pragma unroll 8
            for (int d = 0; d < 128; d++) {
                int dd = (d + tid) & 127;
                acc += S.k[i][dd] * S.k[j][dd];
            }
            val = acc * S.beta[i] * __expf(S.gcs[i] - S.gcs[j]);
        }
        S.A[i][j] = val;
    }
    __syncthreads();
    if (tid < 64) S.T[0][tid] = (tid == 0) ? 1.f : 0.f;
    __syncthreads();
    for (int i = 1; i < 64; i++) {
        if (tid < 64) {
            float acc = 0.f;
            for (int j = 0; j < i; j++) acc += S.A[i][j] * S.T[j][tid];
            S.T[i][tid] = ((tid == i) ? 1.f : 0.f) - acc;
        }
        __syncthreads();
    }
    if (tid < 64) S.coef[tid] = S.beta[tid] * __expf(S.gcs[tid]);
    __syncthreads();
    for (int idx = tid; idx < 64 * 128; idx += 128) {
        int i = idx >> 7, d = idx & 127;
        float au = 0.f, aw = 0.f;
        for (int j = 0; j <= i; j++) {
            float tij = S.T[i][j];
            au += tij * S.x[j][d];
            aw += tij * S.coef[j] * S.k[j][d];
        }
        gu[(size_t)(base + i) * DHEAD + d] = au;
        gw[(size_t)(base + i) * DHEAD + d] = aw;
    }
    __syncthreads();
    for (int idx = tid; idx < 64 * 128; idx += 128) {
        int i = idx >> 7, d = idx & 127;
        S.x[i][d] = gq[(size_t)(base + i) * DHEAD + d];
    }
    __syncthreads();
    float* attn_out = gattn + ((size_t)(h * 64 + n)) * 64 * 64;
    for (int idx = tid; idx < 4096; idx += 128) {
        int i = idx >> 6, j = idx & 63;
        float val = 0.f;
        if (j <= i) {
            float acc = 0.f;
            #pragma unroll 8
            for (int d = 0; d < 128; d++) {
                int dd = (d + tid) & 127;
                acc += S.x[i][dd] * S.k[j][dd];
            }
            val = acc * __expf(S.gcs[i] - S.gcs[j]);
        }
        attn_out[i * 64 + j] = val;
    }
}

// ---------------- sequential scan (512 threads) ----------------
#define DVS 16
struct ScanShm {
    float S[128][DVS];
    float w[64][132];
    float q[64][132];
    float k[64][132];
    float attn[64][68];
    float u[64][DVS];
    float vn[64][DVS];
    float gcs[64];
    float ex[64];
};

__global__ void __launch_bounds__(512) scan_kernel(
    const float* __restrict__ gq, const float* __restrict__ gk, const float* __restrict__ gw,
    const float* __restrict__ gu, const float* __restrict__ gattn, const float* __restrict__ ggcs,
    float* __restrict__ go) {
    ScanShm& S = *(ScanShm*)dyn_smem;
    int h = blockIdx.x;
    int dv0 = blockIdx.y * DVS;
    int tid = threadIdx.x;

    for (int idx = tid; idx < 128 * DVS; idx += 512) S.S[idx >> 4][idx & 15] = 0.f;

    for (int n = 0; n < NCHUNK; n++) {
        int base = h * T_LEN + n * 64;
        if (tid < 64) S.gcs[tid] = ggcs[base + tid];
        for (int idx = tid; idx < 64 * 128; idx += 512) {
            int i = idx >> 7, d = idx & 127;
            size_t gidx = (size_t)(base + i) * DHEAD + d;
            S.w[i][d] = gw[gidx];
            S.q[i][d] = gq[gidx];
            S.k[i][d] = gk[gidx];
        }
        const float* ap = gattn + ((size_t)(h * 64 + n)) * 64 * 64;
        for (int idx = tid; idx < 4096; idx += 512) S.attn[idx >> 6][idx & 63] = ap[idx];
        for (int idx = tid; idx < 64 * DVS; idx += 512) {
            int i = idx >> 4, dv = idx & 15;
            S.u[i][dv] = gu[(size_t)(base + i) * DHEAD + dv0 + dv];
        }
        __syncthreads();
        if (tid < 64) S.ex[tid] = __expf(S.gcs[63] - S.gcs[tid]);

        int i = tid >> 3, dvb = (tid & 7) * 2;
        {
            float2 uv = *(const float2*)&S.u[i][dvb];
            float a0 = uv.x, a1 = uv.y;
            for (int d = 0; d < 128; d++) {
                float wv = S.w[i][d];
                float2 sv = *(const float2*)&S.S[d][dvb];
                a0 -= wv * sv.x; a1 -= wv * sv.y;
            }
            float2 r; r.x = a0; r.y = a1;
            *(float2*)&S.vn[i][dvb] = r;
        }
        __syncthreads();
        {
            float a0 = 0, a1 = 0;
            for (int d = 0; d < 128; d++) {
                float qv = S.q[i][d];
                float2 sv = *(const float2*)&S.S[d][dvb];
                a0 += qv * sv.x; a1 += qv * sv.y;
            }
            float eg = __expf(S.gcs[i]);
            a0 *= eg; a1 *= eg;
            for (int j = 0; j <= i; j++) {
                float av = S.attn[i][j];
                float2 vv = *(const float2*)&S.vn[j][dvb];
                a0 += av * vv.x; a1 += av * vv.y;
            }
            float2 r; r.x = a0; r.y = a1;
            *(float2*)(go + (size_t)(base + i) * DHEAD + dv0 + dvb) = r;
        }
        __syncthreads();
        {
            float gle = __expf(S.gcs[63]);
            #pragma unroll
            for (int r = 0; r < 2; r++) {
                int qi = tid + 512 * r;
                int d = qi >> 3, db = (qi & 7) * 2;
                float2 sv = *(const float2*)&S.S[d][db];
                float a0 = sv.x * gle, a1 = sv.y * gle;
                for (int ii = 0; ii < 64; ii++) {
                    float kk = S.k[ii][d] * S.ex[ii];
                    float2 vv = *(const float2*)&S.vn[ii][db];
                    a0 += kk * vv.x; a1 += kk * vv.y;
                }
                float2 w2; w2.x = a0; w2.y = a1;
                *(float2*)&S.S[d][db] = w2;
            }
        }
        __syncthreads();
    }
}

// ---------------- gated RMSNorm * silu(z) -> fp16 ----------------
__global__ void gated_out_kernel(const float* __restrict__ go, const float* __restrict__ qkvz,
                                 const float* __restrict__ onw, __half* __restrict__ oc16) {
    int h = blockIdx.x, t = blockIdx.y, d = threadIdx.x;
    __shared__ float shm[32];
    float v = go[((size_t)h * T_LEN + t) * DHEAD + d];
    float ss = block_reduce_sum(v * v, shm, d, 128);
    float inv = rsqrtf(ss / 128.f + 1e-5f);
    float z = qkvz[(size_t)t * QKVZ_N + MIX_N + h * 128 + d];
    float res = v * inv * onw[d] * silu_f(z);
    oc16[(size_t)t * DMODEL + h * 128 + d] = __float2half(res);
}

// ---------------- GLU (fp16 in/out, gate buffer updated in place) ----------------
__global__ void glu_kernel(__half* __restrict__ gate16, const __half* __restrict__ up16) {
    int i = blockIdx.x * blockDim.x + threadIdx.x;
    __half2 g2 = ((const __half2*)gate16)[i];
    __half2 u2 = ((const __half2*)up16)[i];
    float2 gf = __half22float2(g2);
    float2 uf = __half22float2(u2);
    gf.x = silu_f(gf.x) * uf.x;
    gf.y = silu_f(gf.y) * uf.y;
    ((__half2*)gate16)[i] = __halves2half2(__float2half(gf.x), __float2half(gf.y));
}

// ---------------- host launch ----------------
extern "C" void kernel_launch(void* const* d_in, const int* in_sizes, int n_in,
                              void* d_out, int out_size) {
    const float* x       = (const float*)d_in[0];
    const float* ln1_w   = (const float*)d_in[2];
    const float* qkvz_w  = (const float*)d_in[3];
    const float* ba_w    = (const float*)d_in[4];
    const float* conv_w  = (const float*)d_in[5];
    const float* A_log   = (const float*)d_in[6];
    const float* dt_bias = (const float*)d_in[7];
    const float* o_norm_w= (const float*)d_in[8];
    const float* out_w   = (const float*)d_in[9];
    const float* ln2_w   = (const float*)d_in[10];
    const float* gate_w  = (const float*)d_in[11];
    const float* up_w    = (const float*)d_in[12];
    const float* down_w  = (const float*)d_in[13];
    float* out = (float*)d_out;

    float *h, *qkvz, *ba, *qb, *kb, *vb, *beta, *gg, *gcs, *u, *w, *attn, *o, *x2;
    cudaGetSymbolAddress((void**)&h,    g_h);
    cudaGetSymbolAddress((void**)&qkvz, g_qkvz);
    cudaGetSymbolAddress((void**)&ba,   g_ba);
    cudaGetSymbolAddress((void**)&qb,   g_qb);
    cudaGetSymbolAddress((void**)&kb,   g_kb);
    cudaGetSymbolAddress((void**)&vb,   g_vb);
    cudaGetSymbolAddress((void**)&beta, g_beta);
    cudaGetSymbolAddress((void**)&gg,   g_g);
    cudaGetSymbolAddress((void**)&gcs,  g_gcs);
    cudaGetSymbolAddress((void**)&u,    g_u);
    cudaGetSymbolAddress((void**)&w,    g_wb);
    cudaGetSymbolAddress((void**)&attn, g_attn);
    cudaGetSymbolAddress((void**)&o,    g_o);
    cudaGetSymbolAddress((void**)&x2,   g_x2);

    __half *h16, *oc16, *qkvz16, *gate16, *up16, *w1, *wo, *wg, *wu, *wd;
    cudaGetSymbolAddress((void**)&h16,    b_h16);
    cudaGetSymbolAddress((void**)&oc16,   b_oc16);
    cudaGetSymbolAddress((void**)&qkvz16, b_qkvz16);
    cudaGetSymbolAddress((void**)&gate16, b_gu16);
    cudaGetSymbolAddress((void**)&up16,   b_up16);
    cudaGetSymbolAddress((void**)&w1,     b_w1);
    cudaGetSymbolAddress((void**)&wo,     b_wo);
    cudaGetSymbolAddress((void**)&wg,     b_wg);
    cudaGetSymbolAddress((void**)&wu,     b_wu);
    cudaGetSymbolAddress((void**)&wd,     b_wd);

    cudaFuncSetAttribute(prep_kernel, cudaFuncAttributeMaxDynamicSharedMemorySize, (int)sizeof(PrepShm));
    cudaFuncSetAttribute(scan_kernel, cudaFuncAttributeMaxDynamicSharedMemorySize, (int)sizeof(ScanShm));
    const int GSMEM = 4 * GSTAGE;  // 64KB -> 2 CTAs/SM
    cudaFuncSetAttribute(gemm_tc, cudaFuncAttributeMaxDynamicSharedMemorySize, GSMEM);

    // weight conversions
    cvt16<<<(QKVZ_N * DMODEL) / 1024, 256>>>(qkvz_w, w1, QKVZ_N * DMODEL);
    cvt16<<<(DMODEL * DMODEL) / 1024, 256>>>(out_w,  wo, DMODEL * DMODEL);
    cvt16<<<(MDIM * DMODEL) / 1024, 256>>>(gate_w, wg, MDIM * DMODEL);
    cvt16<<<(MDIM * DMODEL) / 1024, 256>>>(up_w,   wu, MDIM * DMODEL);
    cvt16<<<(DMODEL * MDIM) / 1024, 256>>>(down_w, wd, DMODEL * MDIM);

    // 1) h = rms(x, ln1) (+ fp16)
    rmsnorm_kernel<<<T_LEN, 256>>>(x, ln1_w, h, h16);
    // 2) qkvz = h @ qkvz_w^T (fp32 + fp16 copy) ; ba = h @ ba_w^T
    gemm_tc<<<dim3(QKVZ_N / 128, T_LEN / 128), 256, GSMEM>>>(h16, w1, (const float*)0, qkvz, qkvz16, T_LEN, QKVZ_N, DMODEL);
    gemm_n32<<<T_LEN / 32, 256>>>(h, ba_w, ba, DMODEL);
    // 3) conv + silu + l2norm (fp16 input)
    conv_kernel<<<dim3(48, T_LEN), 128>>>(qkvz16, conv_w, qb, kb, vb);
    // 4) beta, g, gcs
    betag_kernel<<<(NHEAD * T_LEN + 255) / 256, 256>>>(ba, A_log, dt_bias, beta, gg);
    gcs_kernel<<<NHEAD * NCHUNK, 64>>>(gg, gcs);
    // 5) chunk prep
    prep_kernel<<<dim3(NCHUNK, NHEAD), 128, sizeof(PrepShm)>>>(kb, vb, qb, beta, gcs, u, w, attn);
    // 6) scan
    scan_kernel<<<dim3(NHEAD, DHEAD / DVS), 512, sizeof(ScanShm)>>>(qb, kb, w, u, attn, gcs, o);
    // 7) gated norm * silu(z) -> oc16
    gated_out_kernel<<<dim3(NHEAD, T_LEN), 128>>>(o, qkvz, o_norm_w, oc16);
    // 8) x2 = x + oc @ out_w^T
    gemm_tc<<<dim3(DMODEL / 128, T_LEN / 128), 256, GSMEM>>>(oc16, wo, x, x2, (__half*)0, T_LEN, DMODEL, DMODEL);
    // 9) h2 = rms(x2, ln2)
    rmsnorm_kernel<<<T_LEN, 256>>>(x2, ln2_w, h, h16);
    // 10) gate, up GEMMs (fp16 outputs only)
    gemm_tc<<<dim3(MDIM / 128, T_LEN / 128), 256, GSMEM>>>(h16, wg, (const float*)0, (float*)0, gate16, T_LEN, MDIM, DMODEL);
    gemm_tc<<<dim3(MDIM / 128, T_LEN / 128), 256, GSMEM>>>(h16, wu, (const float*)0, (float*)0, up16, T_LEN, MDIM, DMODEL);
    // 11) gu = silu(gate) * up (fp16, in place in gate16)
    glu_kernel<<<(T_LEN * MDIM / 2) / 256, 256>>>(gate16, up16);
    // 12) out = x2 + gu @ down_w^T
    gemm_tc<<<dim3(DMODEL / 128, T_LEN / 128), 256, GSMEM>>>(gate16, wd, x2, out, (__half*)0, T_LEN, DMODEL, MDIM);
}

// round 15
// speedup vs baseline: 1.2481x; 1.0016x over previous
#include <cuda_runtime.h>
#include <cuda_fp16.h>
#include <math.h>
#include <stdint.h>

// ---------------- Problem constants (B=1) ----------------
#define T_LEN   4096
#define DMODEL  2048
#define NHEAD   16
#define DHEAD   128
#define NCHUNK  64
#define CLEN    64
#define QKVZ_N  8192
#define MIX_N   6144
#define MDIM    8192

// ---------------- fp32 scratch ----------------
__device__ float g_h   [T_LEN * DMODEL];
__device__ float g_ba  [T_LEN * 32];
__device__ float g_qb  [NHEAD * T_LEN * DHEAD];
__device__ float g_kb  [NHEAD * T_LEN * DHEAD];
__device__ float g_vb  [NHEAD * T_LEN * DHEAD];
__device__ float g_beta[NHEAD * T_LEN];
__device__ float g_gcs [NHEAD * T_LEN];
__device__ float g_u   [NHEAD * T_LEN * DHEAD];
__device__ float g_wb  [NHEAD * T_LEN * DHEAD];
__device__ float g_attn[NHEAD * NCHUNK * CLEN * CLEN];
__device__ float g_o   [NHEAD * T_LEN * DHEAD];
__device__ float g_x2  [T_LEN * DMODEL];

// ---------------- fp16 operand scratch ----------------
__device__ __half b_h16   [T_LEN * DMODEL];
__device__ __half b_oc16  [T_LEN * DMODEL];
__device__ __half b_qkvz16[T_LEN * QKVZ_N];
__device__ __half b_gu16  [T_LEN * MDIM];
__device__ __half b_up16  [T_LEN * MDIM];
__device__ __half b_w1 [QKVZ_N * DMODEL];
__device__ __half b_wo [DMODEL * DMODEL];
__device__ __half b_wg [MDIM * DMODEL];
__device__ __half b_wu [MDIM * DMODEL];
__device__ __half b_wd [DMODEL * MDIM];

// ---------------- PTX helpers (sm_103-safe) ----------------
__device__ __forceinline__ uint32_t smem_u32(const void* p) {
    uint32_t a;
    asm("{ .reg .u64 t; cvta.to.shared.u64 t, %1; cvt.u32.u64 %0, t; }" : "=r"(a) : "l"(p));
    return a;
}
#define CP_ASYNC16(d,s) asm volatile("cp.async.cg.shared.global [%0], [%1], 16;" :: "r"(d), "l"(s))
#define CP_COMMIT()     asm volatile("cp.async.commit_group;" ::: "memory")
#define CP_WAIT2()      asm volatile("cp.async.wait_group 2;" ::: "memory")
#define CP_WAIT1()      asm volatile("cp.async.wait_group 1;" ::: "memory")
#define CP_WAIT0()      asm volatile("cp.async.wait_group 0;" ::: "memory")

__device__ __forceinline__ void ldsm4(uint32_t addr, uint32_t* o) {
    uint32_t r0, r1, r2, r3;
    asm volatile("ldmatrix.sync.aligned.m8n8.x4.shared.b16 {%0,%1,%2,%3}, [%4];"
        : "=r"(r0), "=r"(r1), "=r"(r2), "=r"(r3) : "r"(addr));
    o[0] = r0; o[1] = r1; o[2] = r2; o[3] = r3;
}

__device__ __forceinline__ void mma16816(float* d, uint32_t a0, uint32_t a1, uint32_t a2,
                                         uint32_t a3, uint32_t b0, uint32_t b1) {
    float t0 = d[0], t1 = d[1], t2 = d[2], t3 = d[3];
    asm volatile("mma.sync.aligned.m16n8k16.row.col.f32.f16.f16.f32 "
        "{%0,%1,%2,%3},{%4,%5,%6,%7},{%8,%9},{%0,%1,%2,%3};"
        : "+f"(t0), "+f"(t1), "+f"(t2), "+f"(t3)
        : "r"(a0), "r"(a1), "r"(a2), "r"(a3), "r"(b0), "r"(b1));
    d[0] = t0; d[1] = t1; d[2] = t2; d[3] = t3;
}

// ---------------- helpers ----------------
__device__ __forceinline__ float block_reduce_sum(float v, float* shm, int tid, int nthreads) {
    #pragma unroll
    for (int o = 16; o; o >>= 1) v += __shfl_down_sync(0xffffffffu, v, o);
    __syncthreads();
    if ((tid & 31) == 0) shm[tid >> 5] = v;
    __syncthreads();
    int nw = nthreads >> 5;
    float s = (tid < nw) ? shm[tid] : 0.f;
    if (tid < 32) {
        #pragma unroll
        for (int o = 16; o; o >>= 1) s += __shfl_down_sync(0xffffffffu, s, o);
        if (tid == 0) shm[0] = s;
    }
    __syncthreads();
    return shm[0];
}
__device__ __forceinline__ float silu_f(float x) { return x / (1.f + __expf(-x)); }

// ---------------- weight fp32 -> fp16 ----------------
__global__ void cvt16(const float* __restrict__ x, __half* __restrict__ y, int n) {
    int i = (blockIdx.x * blockDim.x + threadIdx.x) * 4;
    if (i >= n) return;
    float4 v = *(const float4*)(x + i);
    __half2* yp = (__half2*)(y + i);
    yp[0] = __halves2half2(__float2half(v.x), __float2half(v.y));
    yp[1] = __halves2half2(__float2half(v.z), __float2half(v.w));
}

// ---------------- RMSNorm + fp16 ----------------
__global__ void rmsnorm_kernel(const float* __restrict__ x, const float* __restrict__ w,
                               float* __restrict__ y, __half* __restrict__ y16) {
    int t = blockIdx.x, tid = threadIdx.x;
    __shared__ float shm[32];
    const float* xr = x + (size_t)t * DMODEL;
    float ss = 0.f;
    for (int d = tid; d < DMODEL; d += 256) { float v = xr[d]; ss += v * v; }
    ss = block_reduce_sum(ss, shm, tid, 256);
    float inv = rsqrtf(ss / (float)DMODEL + 1e-5f);
    for (int d = tid; d < DMODEL; d += 256) {
        float v = xr[d] * inv * w[d];
        y[(size_t)t * DMODEL + d] = v;
        y16[(size_t)t * DMODEL + d] = __float2half(v);
    }
}

// ---------------- HMMA GEMM, 4-buffer / 1-sync pipeline ----------------
// 128x128 tile, BK=32, 8 warps (4x2), warp tile 32x64, 2 CTAs/SM.
// Outputs: fp32 C (optional, +R residual) and/or fp16 H.
#define GSTAGE 16384   // A 8K | B 8K
__global__ void __launch_bounds__(256, 2) gemm_tc(
    const __half* __restrict__ A, const __half* __restrict__ B,
    const float* __restrict__ R, float* __restrict__ C, __half* __restrict__ H,
    int M, int N, int K) {
    extern __shared__ char smem_raw[];
    uint32_t sbase = smem_u32(smem_raw);
    int tid = threadIdx.x, lane = tid & 31, warp = tid >> 5;
    int wm = warp >> 1, wn = warp & 1;
    int m0 = blockIdx.y * 128, n0 = blockIdx.x * 128;
    const int TS = K >> 5;

    float acc[2][8][4];
    #pragma unroll
    for (int a = 0; a < 2; a++)
        #pragma unroll
        for (int b = 0; b < 8; b++)
            #pragma unroll
            for (int c = 0; c < 4; c++) acc[a][b][c] = 0.f;

    uint32_t aoff[2][2], boff[4][2];
    {
        int mat = lane >> 3, r = lane & 7;
        #pragma unroll
        for (int mt = 0; mt < 2; mt++) {
            int row = wm * 32 + mt * 16 + ((mat & 1) << 3) + r;
            #pragma unroll
            for (int ks = 0; ks < 2; ks++) {
                int ch = (ks << 1) + (mat >> 1);
                aoff[mt][ks] = row * 64 + ((ch ^ ((row >> 1) & 3)) << 4);
            }
        }
        #pragma unroll
        for (int j = 0; j < 4; j++) {
            int row = wn * 64 + j * 16 + ((mat >> 1) << 3) + r;
            #pragma unroll
            for (int ks = 0; ks < 2; ks++) {
                int ch = (ks << 1) + (mat & 1);
                boff[j][ks] = 8192 + row * 64 + ((ch ^ ((row >> 1) & 3)) << 4);
            }
        }
    }

    int lrow[2], lc[2]; uint32_t lso[2];
    #pragma unroll
    for (int i = 0; i < 2; i++) {
        int id = (tid << 1) | i;
        lrow[i] = id >> 2; lc[i] = id & 3;
        lso[i] = lrow[i] * 64 + ((lc[i] ^ ((lrow[i] >> 1) & 3)) << 4);
    }

    auto load_stage = [&](int st) {
        int buf = st & 3;
        int k0 = st << 5;
        uint32_t bb = sbase + buf * GSTAGE;
        #pragma unroll
        for (int i = 0; i < 2; i++) {
            CP_ASYNC16(bb + lso[i],        A + (size_t)(m0 + lrow[i]) * K + k0 + lc[i] * 8);
            CP_ASYNC16(bb + 8192 + lso[i], B + (size_t)(n0 + lrow[i]) * K + k0 + lc[i] * 8);
        }
        CP_COMMIT();
    };

    load_stage(0); load_stage(1); load_stage(2);

    for (int st = 0; st < TS; st++) {
        int rem = TS - 1 - st;
        if (rem >= 2) { CP_WAIT2(); } else if (rem == 1) { CP_WAIT1(); } else { CP_WAIT0(); }
        __syncthreads();
        if (st + 3 < TS) load_stage(st + 3);

        uint32_t stb = sbase + (st & 3) * GSTAGE;
        #pragma unroll
        for (int ks = 0; ks < 2; ks++) {
            uint32_t af[2][4], bf[4][4];
            ldsm4(stb + aoff[0][ks], af[0]);
            ldsm4(stb + aoff[1][ks], af[1]);
            #pragma unroll
            for (int j = 0; j < 4; j++) ldsm4(stb + boff[j][ks], bf[j]);
            #pragma unroll
            for (int mt = 0; mt < 2; mt++)
                #pragma unroll
                for (int j = 0; j < 4; j++) {
                    mma16816(&acc[mt][2 * j][0],     af[mt][0], af[mt][1], af[mt][2], af[mt][3], bf[j][0], bf[j][1]);
                    mma16816(&acc[mt][2 * j + 1][0], af[mt][0], af[mt][1], af[mt][2], af[mt][3], bf[j][2], bf[j][3]);
                }
        }
    }

    #pragma unroll
    for (int mt = 0; mt < 2; mt++) {
        #pragma unroll
        for (int nt = 0; nt < 8; nt++) {
            int rr = m0 + wm * 32 + mt * 16 + (lane >> 2);
            int cc = n0 + wn * 64 + nt * 8 + ((lane & 3) << 1);
            float2 v0, v1;
            v0.x = acc[mt][nt][0]; v0.y = acc[mt][nt][1];
            v1.x = acc[mt][nt][2]; v1.y = acc[mt][nt][3];
            if (R != 0) {
                const float2 r0 = *(const float2*)(R + (size_t)rr * N + cc);
                const float2 r1 = *(const float2*)(R + (size_t)(rr + 8) * N + cc);
                v0.x += r0.x; v0.y += r0.y; v1.x += r1.x; v1.y += r1.y;
            }
            if (C != 0) {
                *(float2*)(C + (size_t)rr * N + cc) = v0;
                *(float2*)(C + (size_t)(rr + 8) * N + cc) = v1;
            }
            if (H != 0) {
                *(__half2*)(H + (size_t)rr * N + cc) = __halves2half2(__float2half(v0.x), __float2half(v0.y));
                *(__half2*)(H + (size_t)(rr + 8) * N + cc) = __halves2half2(__float2half(v1.x), __float2half(v1.y));
            }
        }
    }
}

// ---------------- small-N GEMM for ba ----------------
__global__ void gemm_n32(const float* __restrict__ A, const float* __restrict__ B,
                         float* __restrict__ C, int K) {
    __shared__ float hs[32][65];
    __shared__ float ws[32][65];
    int m0 = blockIdx.x * 32;
    int tid = threadIdx.x;
    int c = tid & 31, r0 = tid >> 5;
    float acc[4] = {0, 0, 0, 0};
    for (int k0 = 0; k0 < K; k0 += 64) {
        __syncthreads();
        for (int idx = tid; idx < 2048; idx += 256) {
            int r = idx >> 6, kk = idx & 63;
            hs[r][kk] = A[(size_t)(m0 + r) * K + k0 + kk];
            ws[r][kk] = B[(size_t)r * K + k0 + kk];
        }
        __syncthreads();
        for (int kk = 0; kk < 64; kk++) {
            float wv = ws[c][kk];
            #pragma unroll
            for (int s = 0; s < 4; s++) acc[s] += hs[r0 + 8 * s][kk] * wv;
        }
    }
    #pragma unroll
    for (int s = 0; s < 4; s++) C[(size_t)(m0 + r0 + 8 * s) * 32 + c] = acc[s];
}

// ---------------- causal conv + silu + l2norm (block per t, warp per head, 4 ch/thread) ----------------
__global__ void __launch_bounds__(512) conv_kernel(
    const __half* __restrict__ qkvz16, const float* __restrict__ conv_w,
    float* __restrict__ qo, float* __restrict__ ko, float* __restrict__ vo) {
    int t = blockIdx.x;
    int w = threadIdx.x >> 5, lane = threadIdx.x & 31;
    #pragma unroll
    for (int which = 0; which < 3; which++) {
        int c0 = which * 2048 + w * 128 + lane * 4;   // 4 channels per thread: full 128/head
        float wa[4][4];
        #pragma unroll
        for (int ch = 0; ch < 4; ch++) {
            float4 wv = *(const float4*)(conv_w + (c0 + ch) * 4);
            wa[ch][0] = wv.x; wa[ch][1] = wv.y; wa[ch][2] = wv.z; wa[ch][3] = wv.w;
        }
        float acc[4] = {0.f, 0.f, 0.f, 0.f};
        #pragma unroll
        for (int j = 0; j < 4; j++) {
            int tt = t - 3 + j;
            if (tt >= 0) {
                __half2 v01 = *(const __half2*)(qkvz16 + (size_t)tt * QKVZ_N + c0);
                __half2 v23 = *(const __half2*)(qkvz16 + (size_t)tt * QKVZ_N + c0 + 2);
                float2 f01 = __half22float2(v01);
                float2 f23 = __half22float2(v23);
                acc[0] += f01.x * wa[0][j];
                acc[1] += f01.y * wa[1][j];
                acc[2] += f23.x * wa[2][j];
                acc[3] += f23.y * wa[3][j];
            }
        }
        float s0 = silu_f(acc[0]), s1 = silu_f(acc[1]), s2 = silu_f(acc[2]), s3 = silu_f(acc[3]);
        size_t oidx = ((size_t)w * T_LEN + t) * DHEAD + lane * 4;
        if (which == 2) {
            float4 r; r.x = s0; r.y = s1; r.z = s2; r.w = s3;
            *(float4*)(vo + oidx) = r;
        } else {
            float ss = s0 * s0 + s1 * s1 + s2 * s2 + s3 * s3;
            #pragma unroll
            for (int o = 16; o; o >>= 1) ss += __shfl_xor_sync(0xffffffffu, ss, o);
            float inv = rsqrtf(ss + 1e-6f);
            if (which == 0) inv *= 0.08838834764831845f;
            float4 r; r.x = s0 * inv; r.y = s1 * inv; r.z = s2 * inv; r.w = s3 * inv;
            *(float4*)((which == 0 ? qo : ko) + oidx) = r;
        }
    }
}

// ---------------- fused beta / g / within-chunk cumsum ----------------
__global__ void betag_gcs_kernel(const float* __restrict__ ba, const float* __restrict__ A_log,
                                 const float* __restrict__ dt_bias,
                                 float* __restrict__ beta, float* __restrict__ gcs) {
    int h = blockIdx.x >> 6, n = blockIdx.x & 63;
    int i = threadIdx.x;
    int t = n * 64 + i;
    __shared__ float s[64];
    float b = ba[t * 32 + h];
    float a = ba[t * 32 + 16 + h];
    beta[h * T_LEN + t] = 1.f / (1.f + expf(-b));
    float xx = a + dt_bias[h];
    float sp = (xx > 20.f) ? xx : log1pf(expf(xx));
    s[i] = -expf(A_log[h]) * sp;
    __syncthreads();
    for (int off = 1; off < 64; off <<= 1) {
        float v = (i >= off) ? s[i - off] : 0.f;
        __syncthreads();
        s[i] += v;
        __syncthreads();
    }
    gcs[h * T_LEN + t] = s[i];
}

// ---------------- per-chunk prep: A, T=(I+A)^-1, u, w, attn ----------------
struct PrepShm {
    float k[64][128];
    float x[64][128];
    float A[64][64];
    float T[64][64];
    float gcs[64];
    float beta[64];
    float coef[64];
};
extern __shared__ float dyn_smem[];

__global__ void __launch_bounds__(128) prep_kernel(
    const float* __restrict__ gk, const float* __restrict__ gv, const float* __restrict__ gq,
    const float* __restrict__ gbeta, const float* __restrict__ ggcs,
    float* __restrict__ gu, float* __restrict__ gw, float* __restrict__ gattn) {
    PrepShm& S = *(PrepShm*)dyn_smem;
    int n = blockIdx.x, h = blockIdx.y;
    int tid = threadIdx.x;
    int base = h * T_LEN + n * 64;

    if (tid < 64) {
        S.gcs[tid]  = ggcs[base + tid];
        S.beta[tid] = gbeta[base + tid];
    }
    for (int idx = tid; idx < 64 * 128; idx += 128) {
        int i = idx >> 7, d = idx & 127;
        S.k[i][d] = gk[(size_t)(base + i) * DHEAD + d];
    }
    __syncthreads();
    for (int idx = tid; idx < 64 * 128; idx += 128) {
        int i = idx >> 7, d = idx & 127;
        S.x[i][d] = gv[(size_t)(base + i) * DHEAD + d] * S.beta[i];
    }
    for (int idx = tid; idx < 4096; idx += 128) {
        int i = idx >> 6, j = idx & 63;
        float val = 0.f;
        if (j < i) {
            float acc = 0.f;
            #pragma unroll 8
            for (int d = 0; d < 128; d++) {
                int dd = (d + tid) & 127;
                acc += S.k[i][dd] * S.k[j][dd];
            }
            val = acc * S.beta[i] * __expf(S.gcs[i] - S.gcs[j]);
        }
        S.A[i][j] = val;
    }
    __syncthreads();
    if (tid < 64) S.T[0][tid] = (tid == 0) ? 1.f : 0.f;
    __syncthreads();
    for (int i = 1; i < 64; i++) {
        if (tid < 64) {
            float acc = 0.f;
            for (int j = 0; j < i; j++) acc += S.A[i][j] * S.T[j][tid];
            S.T[i][tid] = ((tid == i) ? 1.f : 0.f) - acc;
        }
        __syncthreads();
    }
    if (tid < 64) S.coef[tid] = S.beta[tid] * __expf(S.gcs[tid]);
    __syncthreads();
    for (int idx = tid; idx < 64 * 128; idx += 128) {
        int i = idx >> 7, d = idx & 127;
        float au = 0.f, aw = 0.f;
        for (int j = 0; j <= i; j++) {
            float tij = S.T[i][j];
            au += tij * S.x[j][d];
            aw += tij * S.coef[j] * S.k[j][d];
        }
        gu[(size_t)(base + i) * DHEAD + d] = au;
        gw[(size_t)(base + i) * DHEAD + d] = aw;
    }
    __syncthreads();
    for (int idx = tid; idx < 64 * 128; idx += 128) {
        int i = idx >> 7, d = idx & 127;
        S.x[i][d] = gq[(size_t)(base + i) * DHEAD + d];
    }
    __syncthreads();
    float* attn_out = gattn + ((size_t)(h * 64 + n)) * 64 * 64;
    for (int idx = tid; idx < 4096; idx += 128) {
        int i = idx >> 6, j = idx & 63;
        float val = 0.f;
        if (j <= i) {
            float acc = 0.f;
            #pragma unroll 8
            for (int d = 0; d < 128; d++) {
                int dd = (d + tid) & 127;
                acc += S.x[i][dd] * S.k[j][dd];
            }
            val = acc * __expf(S.gcs[i] - S.gcs[j]);
        }
        attn_out[i * 64 + j] = val;
    }
}

// ---------------- sequential scan (512 threads) ----------------
#define DVS 16
struct ScanShm {
    float S[128][DVS];
    float w[64][132];
    float q[64][132];
    float k[64][132];
    float attn[64][68];
    float u[64][DVS];
    float vn[64][DVS];
    float gcs[64];
    float ex[64];
};

__global__ void __launch_bounds__(512) scan_kernel(
    const float* __restrict__ gq, const float* __restrict__ gk, const float* __restrict__ gw,
    const float* __restrict__ gu, const float* __restrict__ gattn, const float* __restrict__ ggcs,
    float* __restrict__ go) {
    ScanShm& S = *(ScanShm*)dyn_smem;
    int h = blockIdx.x;
    int dv0 = blockIdx.y * DVS;
    int tid = threadIdx.x;

    for (int idx = tid; idx < 128 * DVS; idx += 512) S.S[idx >> 4][idx & 15] = 0.f;

    for (int n = 0; n < NCHUNK; n++) {
        int base = h * T_LEN + n * 64;
        if (tid < 64) S.gcs[tid] = ggcs[base + tid];
        for (int idx = tid; idx < 64 * 128; idx += 512) {
            int i = idx >> 7, d = idx & 127;
            size_t gidx = (size_t)(base + i) * DHEAD + d;
            S.w[i][d] = gw[gidx];
            S.q[i][d] = gq[gidx];
            S.k[i][d] = gk[gidx];
        }
        const float* ap = gattn + ((size_t)(h * 64 + n)) * 64 * 64;
        for (int idx = tid; idx < 4096; idx += 512) S.attn[idx >> 6][idx & 63] = ap[idx];
        for (int idx = tid; idx < 64 * DVS; idx += 512) {
            int i = idx >> 4, dv = idx & 15;
            S.u[i][dv] = gu[(size_t)(base + i) * DHEAD + dv0 + dv];
        }
        __syncthreads();
        if (tid < 64) S.ex[tid] = __expf(S.gcs[63] - S.gcs[tid]);

        int i = tid >> 3, dvb = (tid & 7) * 2;
        {
            float2 uv = *(const float2*)&S.u[i][dvb];
            float a0 = uv.x, a1 = uv.y;
            for (int d = 0; d < 128; d++) {
                float wv = S.w[i][d];
                float2 sv = *(const float2*)&S.S[d][dvb];
                a0 -= wv * sv.x; a1 -= wv * sv.y;
            }
            float2 r; r.x = a0; r.y = a1;
            *(float2*)&S.vn[i][dvb] = r;
        }
        __syncthreads();
        {
            float a0 = 0, a1 = 0;
            for (int d = 0; d < 128; d++) {
                float qv = S.q[i][d];
                float2 sv = *(const float2*)&S.S[d][dvb];
                a0 += qv * sv.x; a1 += qv * sv.y;
            }
            float eg = __expf(S.gcs[i]);
            a0 *= eg; a1 *= eg;
            for (int j = 0; j <= i; j++) {
                float av = S.attn[i][j];
                float2 vv = *(const float2*)&S.vn[j][dvb];
                a0 += av * vv.x; a1 += av * vv.y;
            }
            float2 r; r.x = a0; r.y = a1;
            *(float2*)(go + (size_t)(base + i) * DHEAD + dv0 + dvb) = r;
        }
        __syncthreads();
        {
            float gle = __expf(S.gcs[63]);
            #pragma unroll
            for (int r = 0; r < 2; r++) {
                int qi = tid + 512 * r;
                int d = qi >> 3, db = (qi & 7) * 2;
                float2 sv = *(const float2*)&S.S[d][db];
                float a0 = sv.x * gle, a1 = sv.y * gle;
                for (int ii = 0; ii < 64; ii++) {
                    float kk = S.k[ii][d] * S.ex[ii];
                    float2 vv = *(const float2*)&S.vn[ii][db];
                    a0 += kk * vv.x; a1 += kk * vv.y;
                }
                float2 w2; w2.x = a0; w2.y = a1;
                *(float2*)&S.S[d][db] = w2;
            }
        }
        __syncthreads();
    }
}

// ---------------- gated RMSNorm * silu(z) -> fp16 (z from fp16 qkvz) ----------------
__global__ void gated_out_kernel(const float* __restrict__ go, const __half* __restrict__ qkvz16,
                                 const float* __restrict__ onw, __half* __restrict__ oc16) {
    int h = blockIdx.x, t = blockIdx.y, d = threadIdx.x;
    __shared__ float shm[32];
    float v = go[((size_t)h * T_LEN + t) * DHEAD + d];
    float ss = block_reduce_sum(v * v, shm, d, 128);
    float inv = rsqrtf(ss / 128.f + 1e-5f);
    float z = __half2float(qkvz16[(size_t)t * QKVZ_N + MIX_N + h * 128 + d]);
    float res = v * inv * onw[d] * silu_f(z);
    oc16[(size_t)t * DMODEL + h * 128 + d] = __float2half(res);
}

// ---------------- GLU (fp16 in/out, gate buffer updated in place) ----------------
__global__ void glu_kernel(__half* __restrict__ gate16, const __half* __restrict__ up16) {
    int i = blockIdx.x * blockDim.x + threadIdx.x;
    __half2 g2 = ((const __half2*)gate16)[i];
    __half2 u2 = ((const __half2*)up16)[i];
    float2 gf = __half22float2(g2);
    float2 uf = __half22float2(u2);
    gf.x = silu_f(gf.x) * uf.x;
    gf.y = silu_f(gf.y) * uf.y;
    ((__half2*)gate16)[i] = __halves2half2(__float2half(gf.x), __float2half(gf.y));
}

// ---------------- host launch ----------------
extern "C" void kernel_launch(void* const* d_in, const int* in_sizes, int n_in,
                              void* d_out, int out_size) {
    const float* x       = (const float*)d_in[0];
    const float* ln1_w   = (const float*)d_in[2];
    const float* qkvz_w  = (const float*)d_in[3];
    const float* ba_w    = (const float*)d_in[4];
    const float* conv_w  = (const float*)d_in[5];
    const float* A_log   = (const float*)d_in[6];
    const float* dt_bias = (const float*)d_in[7];
    const float* o_norm_w= (const float*)d_in[8];
    const float* out_w   = (const float*)d_in[9];
    const float* ln2_w   = (const float*)d_in[10];
    const float* gate_w  = (const float*)d_in[11];
    const float* up_w    = (const float*)d_in[12];
    const float* down_w  = (const float*)d_in[13];
    float* out = (float*)d_out;

    float *h, *ba, *qb, *kb, *vb, *beta, *gcs, *u, *w, *attn, *o, *x2;
    cudaGetSymbolAddress((void**)&h,    g_h);
    cudaGetSymbolAddress((void**)&ba,   g_ba);
    cudaGetSymbolAddress((void**)&qb,   g_qb);
    cudaGetSymbolAddress((void**)&kb,   g_kb);
    cudaGetSymbolAddress((void**)&vb,   g_vb);
    cudaGetSymbolAddress((void**)&beta, g_beta);
    cudaGetSymbolAddress((void**)&gcs,  g_gcs);
    cudaGetSymbolAddress((void**)&u,    g_u);
    cudaGetSymbolAddress((void**)&w,    g_wb);
    cudaGetSymbolAddress((void**)&attn, g_attn);
    cudaGetSymbolAddress((void**)&o,    g_o);
    cudaGetSymbolAddress((void**)&x2,   g_x2);

    __half *h16, *oc16, *qkvz16, *gate16, *up16, *w1, *wo, *wg, *wu, *wd;
    cudaGetSymbolAddress((void**)&h16,    b_h16);
    cudaGetSymbolAddress((void**)&oc16,   b_oc16);
    cudaGetSymbolAddress((void**)&qkvz16, b_qkvz16);
    cudaGetSymbolAddress((void**)&gate16, b_gu16);
    cudaGetSymbolAddress((void**)&up16,   b_up16);
    cudaGetSymbolAddress((void**)&w1,     b_w1);
    cudaGetSymbolAddress((void**)&wo,     b_wo);
    cudaGetSymbolAddress((void**)&wg,     b_wg);
    cudaGetSymbolAddress((void**)&wu,     b_wu);
    cudaGetSymbolAddress((void**)&wd,     b_wd);

    cudaFuncSetAttribute(prep_kernel, cudaFuncAttributeMaxDynamicSharedMemorySize, (int)sizeof(PrepShm));
    cudaFuncSetAttribute(scan_kernel, cudaFuncAttributeMaxDynamicSharedMemorySize, (int)sizeof(ScanShm));
    const int GSMEM = 4 * GSTAGE;  // 64KB -> 2 CTAs/SM
    cudaFuncSetAttribute(gemm_tc, cudaFuncAttributeMaxDynamicSharedMemorySize, GSMEM);

    // weight conversions
    cvt16<<<(QKVZ_N * DMODEL) / 1024, 256>>>(qkvz_w, w1, QKVZ_N * DMODEL);
    cvt16<<<(DMODEL * DMODEL) / 1024, 256>>>(out_w,  wo, DMODEL * DMODEL);
    cvt16<<<(MDIM * DMODEL) / 1024, 256>>>(gate_w, wg, MDIM * DMODEL);
    cvt16<<<(MDIM * DMODEL) / 1024, 256>>>(up_w,   wu, MDIM * DMODEL);
    cvt16<<<(DMODEL * MDIM) / 1024, 256>>>(down_w, wd, DMODEL * MDIM);

    // 1) h = rms(x, ln1) (+ fp16)
    rmsnorm_kernel<<<T_LEN, 256>>>(x, ln1_w, h, h16);
    // 2) qkvz (fp16 only) ; ba = h @ ba_w^T
    gemm_tc<<<dim3(QKVZ_N / 128, T_LEN / 128), 256, GSMEM>>>(h16, w1, (const float*)0, (float*)0, qkvz16, T_LEN, QKVZ_N, DMODEL);
    gemm_n32<<<T_LEN / 32, 256>>>(h, ba_w, ba, DMODEL);
    // 3) conv + silu + l2norm (fp16 input, block per t)
    conv_kernel<<<T_LEN, 512>>>(qkvz16, conv_w, qb, kb, vb);
    // 4) beta + g + gcs (fused)
    betag_gcs_kernel<<<NHEAD * NCHUNK, 64>>>(ba, A_log, dt_bias, beta, gcs);
    // 5) chunk prep
    prep_kernel<<<dim3(NCHUNK, NHEAD), 128, sizeof(PrepShm)>>>(kb, vb, qb, beta, gcs, u, w, attn);
    // 6) scan
    scan_kernel<<<dim3(NHEAD, DHEAD / DVS), 512, sizeof(ScanShm)>>>(qb, kb, w, u, attn, gcs, o);
    // 7) gated norm * silu(z) -> oc16
    gated_out_kernel<<<dim3(NHEAD, T_LEN), 128>>>(o, qkvz16, o_norm_w, oc16);
    // 8) x2 = x + oc @ out_w^T
    gemm_tc<<<dim3(DMODEL / 128, T_LEN / 128), 256, GSMEM>>>(oc16, wo, x, x2, (__half*)0, T_LEN, DMODEL, DMODEL);
    // 9) h2 = rms(x2, ln2)
    rmsnorm_kernel<<<T_LEN, 256>>>(x2, ln2_w, h, h16);
    // 10) gate, up GEMMs (fp16 outputs only)
    gemm_tc<<<dim3(MDIM / 128, T_LEN / 128), 256, GSMEM>>>(h16, wg, (const float*)0, (float*)0, gate16, T_LEN, MDIM, DMODEL);
    gemm_tc<<<dim3(MDIM / 128, T_LEN / 128), 256, GSMEM>>>(h16, wu, (const float*)0, (float*)0, up16, T_LEN, MDIM, DMODEL);
    // 11) gu = silu(gate) * up (fp16, in place in gate16)
    glu_kernel<<<(T_LEN * MDIM / 2) / 256, 256>>>(gate16, up16);
    // 12) out = x2 + gu @ down_w^T
    gemm_tc<<<dim3(DMODEL / 128, T_LEN / 128), 256, GSMEM>>>(gate16, wd, x2, out, (__half*)0, T_LEN, DMODEL, MDIM);
}